// round 9
// baseline (speedup 1.0000x reference)
#include <cuda_runtime.h>
#include <cuda_fp16.h>
#include <cstdint>

#define NW     16384
#define MAXLEN 16
#define VOCAB  128
#define EMB    64
#define HID    256
#define G4     1024
#define SSTRIDE 20                            // slot-tile stride (grid.x)

// ---------------- static device state (no allocation) ----------------
__device__ float d_P[2 * VOCAB * G4];                 // char->gate table incl. biases
__device__ float d_C[(size_t)2 * NW * HID];           // c: [dir][slot][j]
__device__ float d_Hfin[(size_t)2 * NW * HID];        // final h: [dir][slot][j]
// H fp16: [buf][dir][slot][k]
__device__ __align__(16) __half d_Hh[(size_t)2 * 2 * NW * HID];
// W u64-interleaved image: [dir][jb][128 rows][272 halves (68 u64, 64 data + 4 pad)]
__device__ __align__(16) __half d_Wimg[(size_t)2 * 8 * 128 * 272];
__device__ int   d_cursor[MAXLEN + 2];
__device__ int   d_offset[MAXLEN + 2];
__device__ int   d_nactive[MAXLEN];
__device__ int   d_word_of_slot[NW];
__device__ unsigned char d_slot_len[NW];
__device__ unsigned char d_chars[2][MAXLEN][NW];

// ---------------- helpers ----------------
__device__ __forceinline__ float sigm(float x) {
    return __fdividef(1.f, 1.f + __expf(-x));
}
__device__ __forceinline__ void mma_f16(float c[4], const uint32_t a[4],
                                        uint32_t b0, uint32_t b1) {
    asm volatile(
        "mma.sync.aligned.m16n8k16.row.col.f32.f16.f16.f32 "
        "{%0,%1,%2,%3}, {%4,%5,%6,%7}, {%8,%9}, {%0,%1,%2,%3};"
        : "+f"(c[0]), "+f"(c[1]), "+f"(c[2]), "+f"(c[3])
        : "r"(a[0]), "r"(a[1]), "r"(a[2]), "r"(a[3]), "r"(b0), "r"(b1));
}
__device__ __forceinline__ void ldsm4(uint32_t r[4], uint32_t addr) {
    asm volatile("ldmatrix.sync.aligned.m8n8.x4.shared.b16 {%0,%1,%2,%3}, [%4];"
        : "=r"(r[0]), "=r"(r[1]), "=r"(r[2]), "=r"(r[3]) : "r"(addr));
}
__device__ __forceinline__ void lds64(uint32_t& b0, uint32_t& b1, uint32_t addr) {
    asm volatile("ld.shared.v2.b32 {%0,%1}, [%2];" : "=r"(b0), "=r"(b1) : "r"(addr));
}
__device__ __forceinline__ uint32_t smem_u32(const void* p) {
    uint32_t a;
    asm("{ .reg .u64 t; cvta.to.shared.u64 t, %1; cvt.u32.u64 %0, t; }" : "=r"(a) : "l"(p));
    return a;
}
__device__ __forceinline__ void cp16(uint32_t dst, const void* src) {
    asm volatile("cp.async.cg.shared.global [%0], [%1], 16;" :: "r"(dst), "l"(src) : "memory");
}
__device__ __forceinline__ void cp_commit() {
    asm volatile("cp.async.commit_group;" ::: "memory");
}
template <int N>
__device__ __forceinline__ void cp_wait() {
    asm volatile("cp.async.wait_group %0;" :: "n"(N) : "memory");
}

// ---------------- setup: hist + scan + cursor (one block) ----------------
__global__ void k_setup(const int* __restrict__ lengths) {
    __shared__ int sh[MAXLEN + 2];
    int tid = threadIdx.x;                      // 1024
    if (tid <= MAXLEN + 1) sh[tid] = 0;
    __syncthreads();
    for (int w = tid; w < NW; w += 1024) atomicAdd(&sh[lengths[w]], 1);
    __syncthreads();
    if (tid == 0) {
        int off = 0;
        for (int L = MAXLEN; L >= 1; L--) { d_offset[L] = off; off += sh[L]; }
        for (int t = 0; t < MAXLEN; t++) {
            int n = 0;
            for (int L = t + 1; L <= MAXLEN; L++) n += sh[L];
            d_nactive[t] = n;
        }
    }
    if (tid <= MAXLEN + 1) d_cursor[tid] = 0;
}

// ---------------- prep: W u64-interleaved image + P table ----------------
__global__ void k_prep(const float* __restrict__ emb,
                       const float* __restrict__ WihF, const float* __restrict__ bihF,
                       const float* __restrict__ bhhF,
                       const float* __restrict__ WihB, const float* __restrict__ bihB,
                       const float* __restrict__ bhhB,
                       const float* __restrict__ WhhF, const float* __restrict__ WhhB) {
    if (blockIdx.x < 2048) {
        int i = blockIdx.x * 256 + threadIdx.x;    // 2*1024*256
        int dir = i >> 18;
        int e = i & 0x3FFFF;
        int row = e >> 8, k = e & 255;
        int g = row >> 8, j = row & 255;
        int jb = j >> 5, jl = j & 31;
        int r128 = g * 32 + jl;
        // u64 pack: q = (k/16)*4 + (k%8)/2 ; pos = (k%2) + 2*((k%16)>=8)
        int q = (k >> 4) * 4 + ((k & 7) >> 1);
        int pos = (k & 1) + (((k & 15) >= 8) ? 2 : 0);
        float x = (dir ? WhhB : WhhF)[(size_t)row * 256 + k];
        d_Wimg[((size_t)(dir * 8 + jb) * 128 + r128) * 272 + q * 4 + pos] = __float2half_rn(x);
    } else {
        int bid = blockIdx.x - 2048;
        int v = bid & 127, d = bid >> 7;
        const float* Wih = d ? WihB : WihF;
        const float* bih = d ? bihB : bihF;
        const float* bhh = d ? bhhB : bhhF;
        __shared__ float esm[EMB];
        if (threadIdx.x < EMB) esm[threadIdx.x] = emb[v * EMB + threadIdx.x];
        __syncthreads();
#pragma unroll
        for (int q = 0; q < 4; q++) {
            int j = threadIdx.x + q * 256;
            const float* wr = &Wih[j * EMB];
            float s = 0.f;
#pragma unroll
            for (int k = 0; k < EMB; k += 4) {
                float4 wv = *reinterpret_cast<const float4*>(&wr[k]);
                s += esm[k] * wv.x + esm[k + 1] * wv.y + esm[k + 2] * wv.z + esm[k + 3] * wv.w;
            }
            d_P[(d * VOCAB + v) * G4 + j] = s + bih[j] + bhh[j];
        }
    }
}

// ---------------- scatter + step 0 (h0 = 0 -> gates = P[char]) ----------------
__global__ void __launch_bounds__(512)
k_scatter0(const int* __restrict__ lengths, const int* __restrict__ char_ids) {
    int tid = threadIdx.x;
    int wloc = tid >> 3, sub = tid & 7;
    int w = blockIdx.x * 64 + wloc;
    __shared__ int spos[64];
    int len = lengths[w];
    if (sub == 0) {
        int pos = d_offset[len] + atomicAdd(&d_cursor[len], 1);
        spos[wloc] = pos;
        d_word_of_slot[pos] = w;
        d_slot_len[pos] = (unsigned char)len;
#pragma unroll
        for (int t = 0; t < MAXLEN; t++) {
            d_chars[0][t][pos] = (unsigned char)char_ids[w * MAXLEN + t];
            int r = len - 1 - t; if (r < 0) r = 0;
            d_chars[1][t][pos] = (unsigned char)char_ids[w * MAXLEN + r];
        }
    }
    __syncthreads();
    int pos = spos[wloc];
    int dir = sub >> 2;
    int j0 = (sub & 3) * 64;
    int v = char_ids[w * MAXLEN + (dir ? (len - 1) : 0)];
    const float* Pv = &d_P[((dir << 7) + v) << 10];
    bool last = (len == 1);
    float* crow = &d_C[((size_t)dir * NW + pos) * HID];
    float* frow = &d_Hfin[((size_t)dir * NW + pos) * HID];
    __half* hrow = d_Hh + ((size_t)(2 + dir) * NW + pos) * HID;   // buf 1
#pragma unroll 2
    for (int q = 0; q < 64; q += 2) {
        float hv[2];
#pragma unroll
        for (int u = 0; u < 2; u++) {
            int j = j0 + q + u;
            float c1 = sigm(Pv[j]) * tanhf(Pv[512 + j]);
            float h1 = sigm(Pv[768 + j]) * tanhf(c1);
            crow[j] = c1;
            if (last) frow[j] = h1;
            hv[u] = h1;
        }
        __half2 h2v; h2v.x = __float2half_rn(hv[0]); h2v.y = __float2half_rn(hv[1]);
        *reinterpret_cast<__half2*>(&hrow[j0 + q]) = h2v;
    }
}

// ---------------- fused recurrent step (t >= 1), resident W ----------------
// Grid (SSTRIDE, 8 jb, 2 dir). Each block: W tile resident in smem, loops
// slot-tiles bx, bx+SSTRIDE, ... A chunks (64 k) double-buffered via cp.async.
#define TILE_A  18432                         // 128 slots x pitch 144 B
#define TILE_W  69632                         // 128 rows x 544 B (68 u64)
#define SM_W    (2 * TILE_A)                  // 36864
#define SM_TOT  (SM_W + TILE_W)               // 106496

__global__ void __launch_bounds__(256, 2) k_step(int t) {
    const int nact = d_nactive[t];
    const int bx = blockIdx.x;
    const int ntile = (nact + 127) >> 7;
    if (bx >= ntile) return;
    const int myT = (ntile - bx + SSTRIDE - 1) / SSTRIDE;
    const int jb = blockIdx.y, j0 = jb * 32;
    const int dir = blockIdx.z;
    const int rb = t & 1, wb = rb ^ 1;

    extern __shared__ __align__(16) char smem[];
    const uint32_t sb = smem_u32(smem);
    const char* __restrict__ Hr = (const char*)(d_Hh + (size_t)(rb * 2 + dir) * NW * HID);
    const char* wsrc = (const char*)d_Wimg + (size_t)(dir * 8 + jb) * TILE_W;

    const int tid = threadIdx.x;
    const int warp = tid >> 5, lane = tid & 31;
    const int ws = warp & 3, wj = warp >> 2;
    const int g4 = lane >> 2, t4 = lane & 3;

    // ldmatrix per-lane base: row = ws*32 + (lane&15), +16B col for lanes>=16
    const uint32_t arow_off = (uint32_t)(ws * 32 + (lane & 15)) * 144 + ((lane & 16) ? 16 : 0);

    float acc[4][2][2][4];
#pragma unroll
    for (int g = 0; g < 4; g++)
#pragma unroll
        for (int nh = 0; nh < 2; nh++)
#pragma unroll
            for (int mh = 0; mh < 2; mh++)
#pragma unroll
                for (int r = 0; r < 4; r++) acc[g][nh][mh][r] = 0.f;

    auto issue_A = [&](int cc) {
        int tile = cc >> 2, c = cc & 3;
        int s0 = (bx + SSTRIDE * tile) * 128;
        uint32_t dst = sb + (cc & 1) * TILE_A;
#pragma unroll 1
        for (int u = tid; u < 1024; u += 256) {
            int s = u >> 3, ko = u & 7;
            cp16(dst + s * 144 + ko * 16,
                 Hr + (size_t)(s0 + s) * 512 + c * 128 + ko * 16);
        }
    };

    // prologue: W (once) + first two A chunks
#pragma unroll 1
    for (int u = tid; u < 4352; u += 256)
        cp16(sb + SM_W + u * 16, wsrc + u * 16);
    cp_commit();
    const int total_cc = 4 * myT;
    issue_A(0); cp_commit();
    issue_A(1); cp_commit();

#pragma unroll 1
    for (int cc = 0; cc < total_cc; cc++) {
        if (cc + 1 < total_cc) cp_wait<1>(); else cp_wait<0>();
        __syncthreads();
        const int c = cc & 3;
        const uint32_t aB = sb + (cc & 1) * TILE_A + arow_off;
        const uint32_t wB = sb + SM_W;
#pragma unroll
        for (int kk4 = 0; kk4 < 4; kk4++) {
            uint32_t a0[4], a1[4];
            ldsm4(a0, aB + kk4 * 32);
            ldsm4(a1, aB + 2304 + kk4 * 32);      // mh=1: +16 rows * 144
            const int qb = c * 16 + kk4 * 4 + t4;
#pragma unroll
            for (int g = 0; g < 4; g++) {
#pragma unroll
                for (int nh = 0; nh < 2; nh++) {
                    int row = g * 32 + wj * 16 + nh * 8 + g4;
                    uint32_t b0, b1;
                    lds64(b0, b1, wB + (uint32_t)(row * 68 + qb) * 8);
                    mma_f16(acc[g][nh][0], a0, b0, b1);
                    mma_f16(acc[g][nh][1], a1, b0, b1);
                }
            }
        }
        __syncthreads();
        if (cc + 2 < total_cc) { issue_A(cc + 2); cp_commit(); }

        if (c == 3) {
            // ---- epilogue for this tile ----
            int slot0 = (bx + SSTRIDE * (cc >> 2)) * 128;
            __half* HW = d_Hh + (size_t)(wb * 2 + dir) * NW * HID;
#pragma unroll
            for (int mh = 0; mh < 2; mh++) {
#pragma unroll
                for (int rh = 0; rh < 2; rh++) {
                    int s = slot0 + ws * 32 + mh * 16 + rh * 8 + g4;
                    if (s < nact) {
                        int v = d_chars[dir][t][s];
                        const float* Pv = &d_P[((dir << 7) + v) << 10];
                        bool last = (t == (int)d_slot_len[s] - 1);
                        float* crow = &d_C[((size_t)dir * NW + s) * HID];
                        float* frow = &d_Hfin[((size_t)dir * NW + s) * HID];
                        __half* hrow = &HW[(size_t)s * HID];
#pragma unroll
                        for (int nh = 0; nh < 2; nh++) {
                            int jp = j0 + wj * 16 + nh * 8 + 2 * t4;
                            float hv[2];
#pragma unroll
                            for (int cp = 0; cp < 2; cp++) {
                                int j = jp + cp;
                                float ai = acc[0][nh][mh][rh * 2 + cp] + Pv[j];
                                float af = acc[1][nh][mh][rh * 2 + cp] + Pv[256 + j];
                                float ag = acc[2][nh][mh][rh * 2 + cp] + Pv[512 + j];
                                float ao = acc[3][nh][mh][rh * 2 + cp] + Pv[768 + j];
                                float c2 = sigm(af) * crow[j] + sigm(ai) * tanhf(ag);
                                float h2 = sigm(ao) * tanhf(c2);
                                crow[j] = c2;
                                if (last) frow[j] = h2;
                                hv[cp] = h2;
                            }
                            __half2 h2v;
                            h2v.x = __float2half_rn(hv[0]);
                            h2v.y = __float2half_rn(hv[1]);
                            *reinterpret_cast<__half2*>(&hrow[jp]) = h2v;
                        }
                    }
                }
            }
#pragma unroll
            for (int g = 0; g < 4; g++)
#pragma unroll
                for (int nh = 0; nh < 2; nh++)
#pragma unroll
                    for (int mh = 0; mh < 2; mh++)
#pragma unroll
                        for (int r = 0; r < 4; r++) acc[g][nh][mh][r] = 0.f;
        }
    }
}

// ---------------- gather output ----------------
__global__ void k_out(float* __restrict__ out) {
    int s = blockIdx.x;
    int tid = threadIdx.x;
    int w = d_word_of_slot[s];
    int dir = tid >> 8, j = tid & 255;
    out[(size_t)w * 512 + tid] = d_Hfin[((size_t)dir * NW + s) * HID + j];
}

// ---------------- launch ----------------
extern "C" void kernel_launch(void* const* d_in, const int* in_sizes, int n_in,
                              void* d_out, int out_size) {
    const int*   char_ids = (const int*)d_in[0];
    const int*   lengths  = (const int*)d_in[1];
    const float* emb      = (const float*)d_in[2];
    const float* WihF = (const float*)d_in[3];
    const float* WhhF = (const float*)d_in[4];
    const float* bihF = (const float*)d_in[5];
    const float* bhhF = (const float*)d_in[6];
    const float* WihB = (const float*)d_in[7];
    const float* WhhB = (const float*)d_in[8];
    const float* bihB = (const float*)d_in[9];
    const float* bhhB = (const float*)d_in[10];
    float* out = (float*)d_out;

    static bool s_init = false;
    if (!s_init) {
        cudaFuncSetAttribute(k_step, cudaFuncAttributeMaxDynamicSharedMemorySize, SM_TOT);
        s_init = true;
    }

    k_setup<<<1, 1024>>>(lengths);
    k_prep<<<2048 + 256, 256>>>(emb, WihF, bihF, bhhF, WihB, bihB, bhhB, WhhF, WhhB);
    k_scatter0<<<NW / 64, 512>>>(lengths, char_ids);
    for (int t = 1; t < MAXLEN; t++)
        k_step<<<dim3(SSTRIDE, 8, 2), 256, SM_TOT>>>(t);
    k_out<<<NW, 512>>>(out);
}

// round 10
// speedup vs baseline: 1.4232x; 1.4232x over previous
#include <cuda_runtime.h>
#include <cuda_fp16.h>
#include <cstdint>

#define NW     16384
#define MAXLEN 16
#define VOCAB  128
#define EMB    64
#define HID    256
#define G4     1024

// ---------------- static device state (no allocation) ----------------
__device__ float d_P[2 * VOCAB * G4];                 // char->gate table incl. biases
__device__ float d_C[(size_t)2 * NW * HID];           // c: [dir][slot][j]
__device__ float d_Hfin[(size_t)2 * NW * HID];        // final h: [dir][slot][j]
// H fp16: [buf][dir][slot][k]
__device__ __align__(16) __half d_Hh[(size_t)2 * 2 * NW * HID];
// W u64-interleaved, chunked: [dir][jb][chunk(4)][128 rows][pitch 20 u64 = 80 halves]
__device__ __align__(16) __half d_Wimg[(size_t)2 * 8 * 4 * 128 * 80];
__device__ int   d_cursor[MAXLEN + 2];
__device__ int   d_offset[MAXLEN + 2];
__device__ int   d_nactive[MAXLEN];
__device__ int   d_word_of_slot[NW];
__device__ unsigned char d_slot_len[NW];
__device__ unsigned char d_chars[2][MAXLEN][NW];

// ---------------- helpers ----------------
__device__ __forceinline__ float sigm(float x) {
    return __fdividef(1.f, 1.f + __expf(-x));
}
__device__ __forceinline__ void mma_f16(float c[4], const uint32_t a[4],
                                        uint32_t b0, uint32_t b1) {
    asm volatile(
        "mma.sync.aligned.m16n8k16.row.col.f32.f16.f16.f32 "
        "{%0,%1,%2,%3}, {%4,%5,%6,%7}, {%8,%9}, {%0,%1,%2,%3};"
        : "+f"(c[0]), "+f"(c[1]), "+f"(c[2]), "+f"(c[3])
        : "r"(a[0]), "r"(a[1]), "r"(a[2]), "r"(a[3]), "r"(b0), "r"(b1));
}
__device__ __forceinline__ void ldsm4(uint32_t r[4], uint32_t addr) {
    asm volatile("ldmatrix.sync.aligned.m8n8.x4.shared.b16 {%0,%1,%2,%3}, [%4];"
        : "=r"(r[0]), "=r"(r[1]), "=r"(r[2]), "=r"(r[3]) : "r"(addr));
}
__device__ __forceinline__ void lds64(uint32_t& b0, uint32_t& b1, uint32_t addr) {
    asm volatile("ld.shared.v2.b32 {%0,%1}, [%2];" : "=r"(b0), "=r"(b1) : "r"(addr));
}
__device__ __forceinline__ uint32_t smem_u32(const void* p) {
    uint32_t a;
    asm("{ .reg .u64 t; cvta.to.shared.u64 t, %1; cvt.u32.u64 %0, t; }" : "=r"(a) : "l"(p));
    return a;
}
__device__ __forceinline__ void cp16(uint32_t dst, const void* src) {
    asm volatile("cp.async.cg.shared.global [%0], [%1], 16;" :: "r"(dst), "l"(src) : "memory");
}
__device__ __forceinline__ void cp_commit() {
    asm volatile("cp.async.commit_group;" ::: "memory");
}
template <int N>
__device__ __forceinline__ void cp_wait() {
    asm volatile("cp.async.wait_group %0;" :: "n"(N) : "memory");
}

// ---------------- setup: hist + scan + cursor (one block) ----------------
__global__ void k_setup(const int* __restrict__ lengths) {
    __shared__ int sh[MAXLEN + 2];
    int tid = threadIdx.x;                      // 1024
    if (tid <= MAXLEN + 1) sh[tid] = 0;
    __syncthreads();
    for (int w = tid; w < NW; w += 1024) atomicAdd(&sh[lengths[w]], 1);
    __syncthreads();
    if (tid == 0) {
        int off = 0;
        for (int L = MAXLEN; L >= 1; L--) { d_offset[L] = off; off += sh[L]; }
        for (int t = 0; t < MAXLEN; t++) {
            int n = 0;
            for (int L = t + 1; L <= MAXLEN; L++) n += sh[L];
            d_nactive[t] = n;
        }
    }
    if (tid <= MAXLEN + 1) d_cursor[tid] = 0;
}

// ---------------- prep: W u64-interleaved chunked image + P table ----------------
__global__ void k_prep(const float* __restrict__ emb,
                       const float* __restrict__ WihF, const float* __restrict__ bihF,
                       const float* __restrict__ bhhF,
                       const float* __restrict__ WihB, const float* __restrict__ bihB,
                       const float* __restrict__ bhhB,
                       const float* __restrict__ WhhF, const float* __restrict__ WhhB) {
    if (blockIdx.x < 2048) {
        int i = blockIdx.x * 256 + threadIdx.x;    // 2*1024*256
        int dir = i >> 18;
        int e = i & 0x3FFFF;
        int row = e >> 8, k = e & 255;
        int g = row >> 8, j = row & 255;
        int jb = j >> 5, jl = j & 31;
        int r128 = g * 32 + jl;
        int ch = k >> 6, kl = k & 63;
        // u64 pack (chunk-local): q = (kl/16)*4 + (kl%8)/2 ; pos = kl%2 + 2*((kl%16)>=8)
        int q = (kl >> 4) * 4 + ((kl & 7) >> 1);
        int pos = (kl & 1) + (((kl & 15) >= 8) ? 2 : 0);
        float x = (dir ? WhhB : WhhF)[(size_t)row * 256 + k];
        d_Wimg[(((size_t)((dir * 8 + jb) * 4 + ch) * 128 + r128) * 20 + q) * 4 + pos]
            = __float2half_rn(x);
    } else {
        int bid = blockIdx.x - 2048;
        int v = bid & 127, d = bid >> 7;
        const float* Wih = d ? WihB : WihF;
        const float* bih = d ? bihB : bihF;
        const float* bhh = d ? bhhB : bhhF;
        __shared__ float esm[EMB];
        if (threadIdx.x < EMB) esm[threadIdx.x] = emb[v * EMB + threadIdx.x];
        __syncthreads();
#pragma unroll
        for (int q = 0; q < 4; q++) {
            int j = threadIdx.x + q * 256;
            const float* wr = &Wih[j * EMB];
            float s = 0.f;
#pragma unroll
            for (int k = 0; k < EMB; k += 4) {
                float4 wv = *reinterpret_cast<const float4*>(&wr[k]);
                s += esm[k] * wv.x + esm[k + 1] * wv.y + esm[k + 2] * wv.z + esm[k + 3] * wv.w;
            }
            d_P[(d * VOCAB + v) * G4 + j] = s + bih[j] + bhh[j];
        }
    }
}

// ---------------- scatter + step 0 (h0 = 0 -> gates = P[char]) ----------------
__global__ void __launch_bounds__(512)
k_scatter0(const int* __restrict__ lengths, const int* __restrict__ char_ids) {
    int tid = threadIdx.x;
    int wloc = tid >> 3, sub = tid & 7;
    int w = blockIdx.x * 64 + wloc;
    __shared__ int spos[64];
    int len = lengths[w];
    if (sub == 0) {
        int pos = d_offset[len] + atomicAdd(&d_cursor[len], 1);
        spos[wloc] = pos;
        d_word_of_slot[pos] = w;
        d_slot_len[pos] = (unsigned char)len;
#pragma unroll
        for (int t = 0; t < MAXLEN; t++) {
            d_chars[0][t][pos] = (unsigned char)char_ids[w * MAXLEN + t];
            int r = len - 1 - t; if (r < 0) r = 0;
            d_chars[1][t][pos] = (unsigned char)char_ids[w * MAXLEN + r];
        }
    }
    __syncthreads();
    int pos = spos[wloc];
    int dir = sub >> 2;
    int j0 = (sub & 3) * 64;
    int v = char_ids[w * MAXLEN + (dir ? (len - 1) : 0)];
    const float* Pv = &d_P[((dir << 7) + v) << 10];
    bool last = (len == 1);
    float* crow = &d_C[((size_t)dir * NW + pos) * HID];
    float* frow = &d_Hfin[((size_t)dir * NW + pos) * HID];
    __half* hrow = d_Hh + ((size_t)(2 + dir) * NW + pos) * HID;   // buf 1
#pragma unroll 2
    for (int q = 0; q < 64; q += 2) {
        float hv[2];
#pragma unroll
        for (int u = 0; u < 2; u++) {
            int j = j0 + q + u;
            float c1 = sigm(Pv[j]) * tanhf(Pv[512 + j]);
            float h1 = sigm(Pv[768 + j]) * tanhf(c1);
            crow[j] = c1;
            if (last) frow[j] = h1;
            hv[u] = h1;
        }
        __half2 h2v; h2v.x = __float2half_rn(hv[0]); h2v.y = __float2half_rn(hv[1]);
        *reinterpret_cast<__half2*>(&hrow[j0 + q]) = h2v;
    }
}

// ---------------- fused recurrent step (t >= 1) ----------------
// Block: 128 slots x 32 j x 4 gates, 8 warps (ws 0-3: 32 slots, wj 0-1: 16 j).
// A: fp16 [128 slot][pitch 144 B], via ldmatrix.x4.
// W: u64-interleaved [128 row][pitch 20 u64], via LDS.64 (conflict-free).
#define TILE_A  18432                          // 128 * 144
#define TILE_W  20480                          // 128 * 160
#define SM_W0   (2 * TILE_A)                   // 36864
#define SM_TOT  (SM_W0 + 2 * TILE_W)           // 77824
#define W_SEGS  (TILE_W / 16)                  // 1280

__global__ void __launch_bounds__(256, 2) k_step(int t) {
    const int nact = d_nactive[t];
    const int slot0 = blockIdx.x * 128;
    if (slot0 >= nact) return;
    const int jb = blockIdx.y, j0 = jb * 32;
    const int dir = blockIdx.z;
    const int rb = t & 1, wb = rb ^ 1;

    extern __shared__ __align__(16) char smem[];
    const uint32_t sb = smem_u32(smem);
    const char* __restrict__ Hr = (const char*)(d_Hh + (size_t)(rb * 2 + dir) * NW * HID);
    const char* wimg = (const char*)d_Wimg + (size_t)(dir * 8 + jb) * 4 * TILE_W;

    const int tid = threadIdx.x;
    const int warp = tid >> 5, lane = tid & 31;
    const int ws = warp & 3, wj = warp >> 2;
    const int g4 = lane >> 2, t4 = lane & 3;

    // ldmatrix per-lane base: row = ws*32 + (lane&15), +16B for lanes >= 16 (k 8-15)
    const uint32_t arow_off = (uint32_t)(ws * 32 + (lane & 15)) * 144 + ((lane & 16) ? 16 : 0);

    float acc[4][2][2][4];
#pragma unroll
    for (int g = 0; g < 4; g++)
#pragma unroll
        for (int nh = 0; nh < 2; nh++)
#pragma unroll
            for (int mh = 0; mh < 2; mh++)
#pragma unroll
                for (int r = 0; r < 4; r++) acc[g][nh][mh][r] = 0.f;

    auto issue_chunk = [&](int c, int buf) {
        uint32_t asB = sb + buf * TILE_A;
        uint32_t wsB = sb + SM_W0 + buf * TILE_W;
        const char* wsrc = wimg + c * TILE_W;
#pragma unroll 1
        for (int u = tid; u < 1024 + W_SEGS; u += 256) {
            if (u < 1024) {
                int s = u >> 3, ko = u & 7;
                cp16(asB + s * 144 + ko * 16,
                     Hr + (size_t)(slot0 + s) * 512 + c * 128 + ko * 16);
            } else {
                int r = u - 1024;
                cp16(wsB + r * 16, wsrc + r * 16);
            }
        }
    };

    issue_chunk(0, 0); cp_commit();
    issue_chunk(1, 1); cp_commit();

#pragma unroll 1
    for (int c = 0; c < 4; c++) {
        if (c < 3) cp_wait<1>(); else cp_wait<0>();
        __syncthreads();
        const int buf = c & 1;
        const uint32_t aB = sb + buf * TILE_A + arow_off;
        const uint32_t wB = sb + SM_W0 + buf * TILE_W;
#pragma unroll
        for (int kk4 = 0; kk4 < 4; kk4++) {
            uint32_t a0[4], a1[4];
            ldsm4(a0, aB + kk4 * 32);
            ldsm4(a1, aB + 2304 + kk4 * 32);      // mh=1: +16 rows * 144 B
            const int qb = kk4 * 4 + t4;
#pragma unroll
            for (int g = 0; g < 4; g++) {
#pragma unroll
                for (int nh = 0; nh < 2; nh++) {
                    int row = g * 32 + wj * 16 + nh * 8 + g4;
                    uint32_t b0, b1;
                    lds64(b0, b1, wB + (uint32_t)(row * 20 + qb) * 8);
                    mma_f16(acc[g][nh][0], a0, b0, b1);
                    mma_f16(acc[g][nh][1], a1, b0, b1);
                }
            }
        }
        __syncthreads();
        if (c + 2 < 4) { issue_chunk(c + 2, buf); cp_commit(); }
    }

    // ---- epilogue: LSTM cell, all 4 gates thread-local ----
    __half* HW = d_Hh + (size_t)(wb * 2 + dir) * NW * HID;
#pragma unroll
    for (int mh = 0; mh < 2; mh++) {
#pragma unroll
        for (int rh = 0; rh < 2; rh++) {
            int s = slot0 + ws * 32 + mh * 16 + rh * 8 + g4;
            if (s >= nact) continue;
            int v = d_chars[dir][t][s];
            const float* Pv = &d_P[((dir << 7) + v) << 10];
            bool last = (t == (int)d_slot_len[s] - 1);
            float* crow = &d_C[((size_t)dir * NW + s) * HID];
            float* frow = &d_Hfin[((size_t)dir * NW + s) * HID];
            __half* hrow = &HW[(size_t)s * HID];
#pragma unroll
            for (int nh = 0; nh < 2; nh++) {
                int jp = j0 + wj * 16 + nh * 8 + 2 * t4;
                float hv[2];
#pragma unroll
                for (int cp = 0; cp < 2; cp++) {
                    int j = jp + cp;
                    float ai = acc[0][nh][mh][rh * 2 + cp] + Pv[j];
                    float af = acc[1][nh][mh][rh * 2 + cp] + Pv[256 + j];
                    float ag = acc[2][nh][mh][rh * 2 + cp] + Pv[512 + j];
                    float ao = acc[3][nh][mh][rh * 2 + cp] + Pv[768 + j];
                    float c2 = sigm(af) * crow[j] + sigm(ai) * tanhf(ag);
                    float h2 = sigm(ao) * tanhf(c2);
                    crow[j] = c2;
                    if (last) frow[j] = h2;
                    hv[cp] = h2;
                }
                __half2 h2v;
                h2v.x = __float2half_rn(hv[0]);
                h2v.y = __float2half_rn(hv[1]);
                *reinterpret_cast<__half2*>(&hrow[jp]) = h2v;
            }
        }
    }
}

// ---------------- gather output ----------------
__global__ void k_out(float* __restrict__ out) {
    int s = blockIdx.x;
    int tid = threadIdx.x;
    int w = d_word_of_slot[s];
    int dir = tid >> 8, j = tid & 255;
    out[(size_t)w * 512 + tid] = d_Hfin[((size_t)dir * NW + s) * HID + j];
}

// ---------------- launch ----------------
extern "C" void kernel_launch(void* const* d_in, const int* in_sizes, int n_in,
                              void* d_out, int out_size) {
    const int*   char_ids = (const int*)d_in[0];
    const int*   lengths  = (const int*)d_in[1];
    const float* emb      = (const float*)d_in[2];
    const float* WihF = (const float*)d_in[3];
    const float* WhhF = (const float*)d_in[4];
    const float* bihF = (const float*)d_in[5];
    const float* bhhF = (const float*)d_in[6];
    const float* WihB = (const float*)d_in[7];
    const float* WhhB = (const float*)d_in[8];
    const float* bihB = (const float*)d_in[9];
    const float* bhhB = (const float*)d_in[10];
    float* out = (float*)d_out;

    static bool s_init = false;
    if (!s_init) {
        cudaFuncSetAttribute(k_step, cudaFuncAttributeMaxDynamicSharedMemorySize, SM_TOT);
        s_init = true;
    }

    k_setup<<<1, 1024>>>(lengths);
    k_prep<<<2048 + 256, 256>>>(emb, WihF, bihF, bhhF, WihB, bihB, bhhB, WhhF, WhhB);
    k_scatter0<<<NW / 64, 512>>>(lengths, char_ids);
    for (int t = 1; t < MAXLEN; t++)
        k_step<<<dim3(NW / 128, 8, 2), 256, SM_TOT>>>(t);
    k_out<<<NW, 512>>>(out);
}

// round 11
// speedup vs baseline: 1.5392x; 1.0815x over previous
#include <cuda_runtime.h>
#include <cuda_fp16.h>
#include <cstdint>

#define NW     16384
#define MAXLEN 16
#define VOCAB  128
#define EMB    64
#define HID    256
#define G4     1024

// ---------------- static device state (no allocation) ----------------
__device__ float d_P[2 * VOCAB * G4];                 // char->gate table incl. biases
__device__ float d_C[(size_t)2 * NW * HID];           // c: [dir][slot][j]
__device__ float d_Hfin[(size_t)2 * NW * HID];        // final h: [dir][slot][j]
// H fp16: [buf][dir][slot][k]
__device__ __align__(16) __half d_Hh[(size_t)2 * 2 * NW * HID];
// W u64-interleaved, chunked: [dir][jb][chunk(4)][128 rows][pitch 20 u64 = 80 halves]
__device__ __align__(16) __half d_Wimg[(size_t)2 * 8 * 4 * 128 * 80];
__device__ int   d_cursor[MAXLEN + 2];
__device__ int   d_offset[MAXLEN + 2];
__device__ int   d_nactive[MAXLEN];
__device__ int   d_word_of_slot[NW];
__device__ unsigned char d_slot_len[NW];
__device__ unsigned char d_chars[2][MAXLEN][NW];

// ---------------- helpers ----------------
__device__ __forceinline__ float sigm(float x) {
    return __fdividef(1.f, 1.f + __expf(-x));
}
__device__ __forceinline__ float ftanh(float x) {
    float e = __expf(-2.f * x);
    return __fdividef(1.f - e, 1.f + e);
}
__device__ __forceinline__ void mma_f16(float c[4], const uint32_t a[4],
                                        uint32_t b0, uint32_t b1) {
    asm volatile(
        "mma.sync.aligned.m16n8k16.row.col.f32.f16.f16.f32 "
        "{%0,%1,%2,%3}, {%4,%5,%6,%7}, {%8,%9}, {%0,%1,%2,%3};"
        : "+f"(c[0]), "+f"(c[1]), "+f"(c[2]), "+f"(c[3])
        : "r"(a[0]), "r"(a[1]), "r"(a[2]), "r"(a[3]), "r"(b0), "r"(b1));
}
__device__ __forceinline__ void ldsm4(uint32_t r[4], uint32_t addr) {
    asm volatile("ldmatrix.sync.aligned.m8n8.x4.shared.b16 {%0,%1,%2,%3}, [%4];"
        : "=r"(r[0]), "=r"(r[1]), "=r"(r[2]), "=r"(r[3]) : "r"(addr));
}
__device__ __forceinline__ void lds64(uint32_t& b0, uint32_t& b1, uint32_t addr) {
    asm volatile("ld.shared.v2.b32 {%0,%1}, [%2];" : "=r"(b0), "=r"(b1) : "r"(addr));
}
__device__ __forceinline__ uint32_t smem_u32(const void* p) {
    uint32_t a;
    asm("{ .reg .u64 t; cvta.to.shared.u64 t, %1; cvt.u32.u64 %0, t; }" : "=r"(a) : "l"(p));
    return a;
}
__device__ __forceinline__ void cp16(uint32_t dst, const void* src) {
    asm volatile("cp.async.cg.shared.global [%0], [%1], 16;" :: "r"(dst), "l"(src) : "memory");
}
__device__ __forceinline__ void cp_commit() {
    asm volatile("cp.async.commit_group;" ::: "memory");
}
template <int N>
__device__ __forceinline__ void cp_wait() {
    asm volatile("cp.async.wait_group %0;" :: "n"(N) : "memory");
}

// ---------------- setup: hist + scan + cursor (one block) ----------------
__global__ void k_setup(const int* __restrict__ lengths) {
    __shared__ int sh[MAXLEN + 2];
    int tid = threadIdx.x;                      // 1024
    if (tid <= MAXLEN + 1) sh[tid] = 0;
    __syncthreads();
    for (int w = tid; w < NW; w += 1024) atomicAdd(&sh[lengths[w]], 1);
    __syncthreads();
    if (tid == 0) {
        int off = 0;
        for (int L = MAXLEN; L >= 1; L--) { d_offset[L] = off; off += sh[L]; }
        for (int t = 0; t < MAXLEN; t++) {
            int n = 0;
            for (int L = t + 1; L <= MAXLEN; L++) n += sh[L];
            d_nactive[t] = n;
        }
    }
    if (tid <= MAXLEN + 1) d_cursor[tid] = 0;
}

// ---------------- prep: W u64-interleaved chunked image + P table ----------------
__global__ void k_prep(const float* __restrict__ emb,
                       const float* __restrict__ WihF, const float* __restrict__ bihF,
                       const float* __restrict__ bhhF,
                       const float* __restrict__ WihB, const float* __restrict__ bihB,
                       const float* __restrict__ bhhB,
                       const float* __restrict__ WhhF, const float* __restrict__ WhhB) {
    if (blockIdx.x < 2048) {
        int i = blockIdx.x * 256 + threadIdx.x;    // 2*1024*256
        int dir = i >> 18;
        int e = i & 0x3FFFF;
        int row = e >> 8, k = e & 255;
        int g = row >> 8, j = row & 255;
        int jb = j >> 5, jl = j & 31;
        int r128 = g * 32 + jl;
        int ch = k >> 6, kl = k & 63;
        int q = (kl >> 4) * 4 + ((kl & 7) >> 1);
        int pos = (kl & 1) + (((kl & 15) >= 8) ? 2 : 0);
        float x = (dir ? WhhB : WhhF)[(size_t)row * 256 + k];
        d_Wimg[(((size_t)((dir * 8 + jb) * 4 + ch) * 128 + r128) * 20 + q) * 4 + pos]
            = __float2half_rn(x);
    } else {
        int bid = blockIdx.x - 2048;
        int v = bid & 127, d = bid >> 7;
        const float* Wih = d ? WihB : WihF;
        const float* bih = d ? bihB : bihF;
        const float* bhh = d ? bhhB : bhhF;
        __shared__ float esm[EMB];
        if (threadIdx.x < EMB) esm[threadIdx.x] = emb[v * EMB + threadIdx.x];
        __syncthreads();
#pragma unroll
        for (int q = 0; q < 4; q++) {
            int j = threadIdx.x + q * 256;
            const float* wr = &Wih[j * EMB];
            float s = 0.f;
#pragma unroll
            for (int k = 0; k < EMB; k += 4) {
                float4 wv = *reinterpret_cast<const float4*>(&wr[k]);
                s += esm[k] * wv.x + esm[k + 1] * wv.y + esm[k + 2] * wv.z + esm[k + 3] * wv.w;
            }
            d_P[(d * VOCAB + v) * G4 + j] = s + bih[j] + bhh[j];
        }
    }
}

// ---------------- scatter + step 0 (h0 = 0 -> gates = P[char]) ----------------
__global__ void __launch_bounds__(512)
k_scatter0(const int* __restrict__ lengths, const int* __restrict__ char_ids) {
    int tid = threadIdx.x;
    int wloc = tid >> 3, sub = tid & 7;
    int w = blockIdx.x * 64 + wloc;
    __shared__ int spos[64];
    int len = lengths[w];
    if (sub == 0) {
        int pos = d_offset[len] + atomicAdd(&d_cursor[len], 1);
        spos[wloc] = pos;
        d_word_of_slot[pos] = w;
        d_slot_len[pos] = (unsigned char)len;
#pragma unroll
        for (int t = 0; t < MAXLEN; t++) {
            d_chars[0][t][pos] = (unsigned char)char_ids[w * MAXLEN + t];
            int r = len - 1 - t; if (r < 0) r = 0;
            d_chars[1][t][pos] = (unsigned char)char_ids[w * MAXLEN + r];
        }
    }
    __syncthreads();
    int pos = spos[wloc];
    int dir = sub >> 2;
    int j0 = (sub & 3) * 64;
    int v = char_ids[w * MAXLEN + (dir ? (len - 1) : 0)];
    const float* Pv = &d_P[((dir << 7) + v) << 10];
    bool last = (len == 1);
    float* crow = &d_C[((size_t)dir * NW + pos) * HID];
    float* frow = &d_Hfin[((size_t)dir * NW + pos) * HID];
    __half* hrow = d_Hh + ((size_t)(2 + dir) * NW + pos) * HID;   // buf 1
#pragma unroll 2
    for (int q = 0; q < 64; q += 2) {
        float hv[2];
#pragma unroll
        for (int u = 0; u < 2; u++) {
            int j = j0 + q + u;
            float c1 = sigm(Pv[j]) * ftanh(Pv[512 + j]);
            float h1 = sigm(Pv[768 + j]) * ftanh(c1);
            crow[j] = c1;
            if (last) frow[j] = h1;
            hv[u] = h1;
        }
        __half2 h2v; h2v.x = __float2half_rn(hv[0]); h2v.y = __float2half_rn(hv[1]);
        *reinterpret_cast<__half2*>(&hrow[j0 + q]) = h2v;
    }
}

// ---------------- fused recurrent step (t >= 1) ----------------
// Block: 64 slots x 32 j x 4 gates, 8 warps (ws 0-3: 16 slots, wj 0-1: 16 j).
// A: fp16 [64 slot][pitch 144 B] via ldmatrix.x4 (one per kk4).
// W: u64-interleaved [128 row][pitch 20 u64] via LDS.64 (conflict-free).
#define TILE_A  9216                           // 64 * 144
#define TILE_W  20480                          // 128 * 160
#define SM_W0   (2 * TILE_A)                   // 18432
#define SM_TOT  (SM_W0 + 2 * TILE_W)           // 59392
#define W_SEGS  (TILE_W / 16)                  // 1280

__global__ void __launch_bounds__(256, 3) k_step(int t) {
    const int nact = d_nactive[t];
    const int slot0 = blockIdx.x * 64;
    if (slot0 >= nact) return;
    const int jb = blockIdx.y, j0 = jb * 32;
    const int dir = blockIdx.z;
    const int rb = t & 1, wb = rb ^ 1;

    extern __shared__ __align__(16) char smem[];
    const uint32_t sb = smem_u32(smem);
    const char* __restrict__ Hr = (const char*)(d_Hh + (size_t)(rb * 2 + dir) * NW * HID);
    const char* wimg = (const char*)d_Wimg + (size_t)(dir * 8 + jb) * 4 * TILE_W;

    const int tid = threadIdx.x;
    const int warp = tid >> 5, lane = tid & 31;
    const int ws = warp & 3, wj = warp >> 2;
    const int g4 = lane >> 2, t4 = lane & 3;

    // ldmatrix per-lane base: row = ws*16 + (lane&15), +16B for lanes >= 16 (k 8-15)
    const uint32_t arow_off = (uint32_t)(ws * 16 + (lane & 15)) * 144 + ((lane & 16) ? 16 : 0);

    float acc[4][2][4];
#pragma unroll
    for (int g = 0; g < 4; g++)
#pragma unroll
        for (int nh = 0; nh < 2; nh++)
#pragma unroll
            for (int r = 0; r < 4; r++) acc[g][nh][r] = 0.f;

    auto issue_chunk = [&](int c, int buf) {
        uint32_t asB = sb + buf * TILE_A;
        uint32_t wsB = sb + SM_W0 + buf * TILE_W;
        const char* wsrc = wimg + c * TILE_W;
#pragma unroll 1
        for (int u = tid; u < 512 + W_SEGS; u += 256) {
            if (u < 512) {
                int s = u >> 3, ko = u & 7;
                cp16(asB + s * 144 + ko * 16,
                     Hr + (size_t)(slot0 + s) * 512 + c * 128 + ko * 16);
            } else {
                int r = u - 512;
                cp16(wsB + r * 16, wsrc + r * 16);
            }
        }
    };

    issue_chunk(0, 0); cp_commit();
    issue_chunk(1, 1); cp_commit();

#pragma unroll 1
    for (int c = 0; c < 4; c++) {
        if (c < 3) cp_wait<1>(); else cp_wait<0>();
        __syncthreads();
        const int buf = c & 1;
        const uint32_t aB = sb + buf * TILE_A + arow_off;
        const uint32_t wB = sb + SM_W0 + buf * TILE_W;
#pragma unroll
        for (int kk4 = 0; kk4 < 4; kk4++) {
            uint32_t a0[4];
            ldsm4(a0, aB + kk4 * 32);
            const int qb = kk4 * 4 + t4;
#pragma unroll
            for (int g = 0; g < 4; g++) {
#pragma unroll
                for (int nh = 0; nh < 2; nh++) {
                    int row = g * 32 + wj * 16 + nh * 8 + g4;
                    uint32_t b0, b1;
                    lds64(b0, b1, wB + (uint32_t)(row * 20 + qb) * 8);
                    mma_f16(acc[g][nh], a0, b0, b1);
                }
            }
        }
        __syncthreads();
        if (c + 2 < 4) { issue_chunk(c + 2, buf); cp_commit(); }
    }

    // ---- epilogue: LSTM cell, all 4 gates thread-local (8 cells/thread) ----
    __half* HW = d_Hh + (size_t)(wb * 2 + dir) * NW * HID;
#pragma unroll
    for (int rh = 0; rh < 2; rh++) {
        int s = slot0 + ws * 16 + rh * 8 + g4;
        if (s >= nact) continue;
        int v = d_chars[dir][t][s];
        const float* Pv = &d_P[((dir << 7) + v) << 10];
        bool last = (t == (int)d_slot_len[s] - 1);
        float* crow = &d_C[((size_t)dir * NW + s) * HID];
        float* frow = &d_Hfin[((size_t)dir * NW + s) * HID];
        __half* hrow = &HW[(size_t)s * HID];
#pragma unroll
        for (int nh = 0; nh < 2; nh++) {
            int jp = j0 + wj * 16 + nh * 8 + 2 * t4;
            float hv[2];
#pragma unroll
            for (int cp = 0; cp < 2; cp++) {
                int j = jp + cp;
                float ai = acc[0][nh][rh * 2 + cp] + Pv[j];
                float af = acc[1][nh][rh * 2 + cp] + Pv[256 + j];
                float ag = acc[2][nh][rh * 2 + cp] + Pv[512 + j];
                float ao = acc[3][nh][rh * 2 + cp] + Pv[768 + j];
                float c2 = sigm(af) * crow[j] + sigm(ai) * ftanh(ag);
                float h2 = sigm(ao) * ftanh(c2);
                crow[j] = c2;
                if (last) frow[j] = h2;
                hv[cp] = h2;
            }
            __half2 h2v;
            h2v.x = __float2half_rn(hv[0]);
            h2v.y = __float2half_rn(hv[1]);
            *reinterpret_cast<__half2*>(&hrow[jp]) = h2v;
        }
    }
}

// ---------------- gather output ----------------
__global__ void k_out(float* __restrict__ out) {
    int s = blockIdx.x;
    int tid = threadIdx.x;
    int w = d_word_of_slot[s];
    int dir = tid >> 8, j = tid & 255;
    out[(size_t)w * 512 + tid] = d_Hfin[((size_t)dir * NW + s) * HID + j];
}

// ---------------- launch ----------------
extern "C" void kernel_launch(void* const* d_in, const int* in_sizes, int n_in,
                              void* d_out, int out_size) {
    const int*   char_ids = (const int*)d_in[0];
    const int*   lengths  = (const int*)d_in[1];
    const float* emb      = (const float*)d_in[2];
    const float* WihF = (const float*)d_in[3];
    const float* WhhF = (const float*)d_in[4];
    const float* bihF = (const float*)d_in[5];
    const float* bhhF = (const float*)d_in[6];
    const float* WihB = (const float*)d_in[7];
    const float* WhhB = (const float*)d_in[8];
    const float* bihB = (const float*)d_in[9];
    const float* bhhB = (const float*)d_in[10];
    float* out = (float*)d_out;

    static bool s_init = false;
    if (!s_init) {
        cudaFuncSetAttribute(k_step, cudaFuncAttributeMaxDynamicSharedMemorySize, SM_TOT);
        s_init = true;
    }

    k_setup<<<1, 1024>>>(lengths);
    k_prep<<<2048 + 256, 256>>>(emb, WihF, bihF, bhhF, WihB, bihB, bhhB, WhhF, WhhB);
    k_scatter0<<<NW / 64, 512>>>(lengths, char_ids);
    for (int t = 1; t < MAXLEN; t++)
        k_step<<<dim3(NW / 64, 8, 2), 256, SM_TOT>>>(t);
    k_out<<<NW, 512>>>(out);
}

// round 12
// speedup vs baseline: 1.5592x; 1.0130x over previous
#include <cuda_runtime.h>
#include <cuda_fp16.h>
#include <cstdint>

#define NW     16384
#define MAXLEN 16
#define VOCAB  128
#define EMB    64
#define HID    256
#define G4     1024

// ---------------- static device state (no allocation) ----------------
__device__ float d_P[2 * VOCAB * G4];                 // char->gate table incl. biases
__device__ float d_C[(size_t)2 * NW * HID];           // c: [dir][slot][j]
__device__ float d_Hfin[(size_t)2 * NW * HID];        // final h: [dir][slot][j]
// H fp16: [buf][dir][slot][k]
__device__ __align__(16) __half d_Hh[(size_t)2 * 2 * NW * HID];
// W u64-interleaved, chunked: [dir][jb][chunk(4)][128 rows][pitch 20 u64 = 80 halves]
__device__ __align__(16) __half d_Wimg[(size_t)2 * 8 * 4 * 128 * 80];
__device__ int   d_cursor[MAXLEN + 2];
__device__ int   d_offset[MAXLEN + 2];
__device__ int   d_nactive[MAXLEN];
__device__ int   d_word_of_slot[NW];
__device__ unsigned char d_slot_len[NW];
__device__ unsigned char d_chars[2][MAXLEN][NW];

// ---------------- helpers ----------------
__device__ __forceinline__ float sigm(float x) {
    return __fdividef(1.f, 1.f + __expf(-x));
}
__device__ __forceinline__ float ftanh(float x) {
    float e = __expf(-2.f * x);
    return __fdividef(1.f - e, 1.f + e);
}
__device__ __forceinline__ void mma_f16(float c[4], const uint32_t a[4],
                                        uint32_t b0, uint32_t b1) {
    asm volatile(
        "mma.sync.aligned.m16n8k16.row.col.f32.f16.f16.f32 "
        "{%0,%1,%2,%3}, {%4,%5,%6,%7}, {%8,%9}, {%0,%1,%2,%3};"
        : "+f"(c[0]), "+f"(c[1]), "+f"(c[2]), "+f"(c[3])
        : "r"(a[0]), "r"(a[1]), "r"(a[2]), "r"(a[3]), "r"(b0), "r"(b1));
}
__device__ __forceinline__ void ldsm4(uint32_t r[4], uint32_t addr) {
    asm volatile("ldmatrix.sync.aligned.m8n8.x4.shared.b16 {%0,%1,%2,%3}, [%4];"
        : "=r"(r[0]), "=r"(r[1]), "=r"(r[2]), "=r"(r[3]) : "r"(addr));
}
__device__ __forceinline__ void lds64(uint32_t& b0, uint32_t& b1, uint32_t addr) {
    asm volatile("ld.shared.v2.b32 {%0,%1}, [%2];" : "=r"(b0), "=r"(b1) : "r"(addr));
}
__device__ __forceinline__ uint32_t smem_u32(const void* p) {
    uint32_t a;
    asm("{ .reg .u64 t; cvta.to.shared.u64 t, %1; cvt.u32.u64 %0, t; }" : "=r"(a) : "l"(p));
    return a;
}
__device__ __forceinline__ void cp16(uint32_t dst, const void* src) {
    asm volatile("cp.async.cg.shared.global [%0], [%1], 16;" :: "r"(dst), "l"(src) : "memory");
}
__device__ __forceinline__ void cp_commit() {
    asm volatile("cp.async.commit_group;" ::: "memory");
}
template <int N>
__device__ __forceinline__ void cp_wait() {
    asm volatile("cp.async.wait_group %0;" :: "n"(N) : "memory");
}

// ---------------- setup: hist + scan + cursor (one block) ----------------
__global__ void k_setup(const int* __restrict__ lengths) {
    __shared__ int sh[MAXLEN + 2];
    int tid = threadIdx.x;                      // 1024
    if (tid <= MAXLEN + 1) sh[tid] = 0;
    __syncthreads();
    for (int w = tid; w < NW; w += 1024) atomicAdd(&sh[lengths[w]], 1);
    __syncthreads();
    if (tid == 0) {
        int off = 0;
        for (int L = MAXLEN; L >= 1; L--) { d_offset[L] = off; off += sh[L]; }
        for (int t = 0; t < MAXLEN; t++) {
            int n = 0;
            for (int L = t + 1; L <= MAXLEN; L++) n += sh[L];
            d_nactive[t] = n;
        }
    }
    if (tid <= MAXLEN + 1) d_cursor[tid] = 0;
}

// ---------------- prep: W u64-interleaved chunked image + P table ----------------
__global__ void k_prep(const float* __restrict__ emb,
                       const float* __restrict__ WihF, const float* __restrict__ bihF,
                       const float* __restrict__ bhhF,
                       const float* __restrict__ WihB, const float* __restrict__ bihB,
                       const float* __restrict__ bhhB,
                       const float* __restrict__ WhhF, const float* __restrict__ WhhB) {
    if (blockIdx.x < 2048) {
        int i = blockIdx.x * 256 + threadIdx.x;    // 2*1024*256
        int dir = i >> 18;
        int e = i & 0x3FFFF;
        int row = e >> 8, k = e & 255;
        int g = row >> 8, j = row & 255;
        int jb = j >> 5, jl = j & 31;
        int r128 = g * 32 + jl;
        int ch = k >> 6, kl = k & 63;
        int q = (kl >> 4) * 4 + ((kl & 7) >> 1);
        int pos = (kl & 1) + (((kl & 15) >= 8) ? 2 : 0);
        float x = (dir ? WhhB : WhhF)[(size_t)row * 256 + k];
        d_Wimg[(((size_t)((dir * 8 + jb) * 4 + ch) * 128 + r128) * 20 + q) * 4 + pos]
            = __float2half_rn(x);
    } else {
        int bid = blockIdx.x - 2048;
        int v = bid & 127, d = bid >> 7;
        const float* Wih = d ? WihB : WihF;
        const float* bih = d ? bihB : bihF;
        const float* bhh = d ? bhhB : bhhF;
        __shared__ float esm[EMB];
        if (threadIdx.x < EMB) esm[threadIdx.x] = emb[v * EMB + threadIdx.x];
        __syncthreads();
#pragma unroll
        for (int q = 0; q < 4; q++) {
            int j = threadIdx.x + q * 256;
            const float* wr = &Wih[j * EMB];
            float s = 0.f;
#pragma unroll
            for (int k = 0; k < EMB; k += 4) {
                float4 wv = *reinterpret_cast<const float4*>(&wr[k]);
                s += esm[k] * wv.x + esm[k + 1] * wv.y + esm[k + 2] * wv.z + esm[k + 3] * wv.w;
            }
            d_P[(d * VOCAB + v) * G4 + j] = s + bih[j] + bhh[j];
        }
    }
}

// ---------------- scatter + step 0 (h0 = 0 -> gates = P[char]) ----------------
__global__ void __launch_bounds__(512)
k_scatter0(const int* __restrict__ lengths, const int* __restrict__ char_ids) {
    int tid = threadIdx.x;
    int wloc = tid >> 3, sub = tid & 7;
    int w = blockIdx.x * 64 + wloc;
    __shared__ int spos[64];
    int len = lengths[w];
    if (sub == 0) {
        int pos = d_offset[len] + atomicAdd(&d_cursor[len], 1);
        spos[wloc] = pos;
        d_word_of_slot[pos] = w;
        d_slot_len[pos] = (unsigned char)len;
#pragma unroll
        for (int t = 0; t < MAXLEN; t++) {
            d_chars[0][t][pos] = (unsigned char)char_ids[w * MAXLEN + t];
            int r = len - 1 - t; if (r < 0) r = 0;
            d_chars[1][t][pos] = (unsigned char)char_ids[w * MAXLEN + r];
        }
    }
    __syncthreads();
    int pos = spos[wloc];
    int dir = sub >> 2;
    int j0 = (sub & 3) * 64;
    int v = char_ids[w * MAXLEN + (dir ? (len - 1) : 0)];
    const float* Pv = &d_P[((dir << 7) + v) << 10];
    bool last = (len == 1);
    float* crow = &d_C[((size_t)dir * NW + pos) * HID];
    float* frow = &d_Hfin[((size_t)dir * NW + pos) * HID];
    __half* hrow = d_Hh + ((size_t)(2 + dir) * NW + pos) * HID;   // buf 1
#pragma unroll 2
    for (int q = 0; q < 64; q += 2) {
        float hv[2];
#pragma unroll
        for (int u = 0; u < 2; u++) {
            int j = j0 + q + u;
            float c1 = sigm(Pv[j]) * ftanh(Pv[512 + j]);
            float h1 = sigm(Pv[768 + j]) * ftanh(c1);
            crow[j] = c1;
            if (last) frow[j] = h1;
            hv[u] = h1;
        }
        __half2 h2v; h2v.x = __float2half_rn(hv[0]); h2v.y = __float2half_rn(hv[1]);
        *reinterpret_cast<__half2*>(&hrow[j0 + q]) = h2v;
    }
}

// ---------------- fused recurrent step (t >= 1) ----------------
// Block: 64 slots x 32 j x 4 gates, 8 warps. Warp tile 32 slots x 32 n (square):
// ws = warp&1 (32 slots, 2 LDSM frags), wj = warp>>1 (8 j = 32 n with gates).
// A: fp16 [64 slot][pitch 144 B] via ldmatrix.x4 x2 per kk4.
// W: u64-interleaved [128 row][pitch 20 u64] via LDS.64 (conflict-free), each
// B fragment feeds 2 MMAs (mh pair).
#define TILE_A  9216                           // 64 * 144
#define TILE_W  20480                          // 128 * 160
#define SM_W0   (2 * TILE_A)                   // 18432
#define SM_TOT  (SM_W0 + 2 * TILE_W)           // 59392
#define W_SEGS  (TILE_W / 16)                  // 1280

__global__ void __launch_bounds__(256, 3) k_step(int t) {
    const int nact = d_nactive[t];
    const int slot0 = blockIdx.x * 64;
    if (slot0 >= nact) return;
    const int jb = blockIdx.y, j0 = jb * 32;
    const int dir = blockIdx.z;
    const int rb = t & 1, wb = rb ^ 1;

    extern __shared__ __align__(16) char smem[];
    const uint32_t sb = smem_u32(smem);
    const char* __restrict__ Hr = (const char*)(d_Hh + (size_t)(rb * 2 + dir) * NW * HID);
    const char* wimg = (const char*)d_Wimg + (size_t)(dir * 8 + jb) * 4 * TILE_W;

    const int tid = threadIdx.x;
    const int warp = tid >> 5, lane = tid & 31;
    const int ws = warp & 1, wj = warp >> 1;
    const int g4 = lane >> 2, t4 = lane & 3;

    // ldmatrix per-lane base: row = ws*32 + (lane&15), +16B for lanes >= 16 (k 8-15)
    const uint32_t arow_off = (uint32_t)(ws * 32 + (lane & 15)) * 144 + ((lane & 16) ? 16 : 0);

    float acc[4][2][4];                        // [gate][mh][frag]
#pragma unroll
    for (int g = 0; g < 4; g++)
#pragma unroll
        for (int mh = 0; mh < 2; mh++)
#pragma unroll
            for (int r = 0; r < 4; r++) acc[g][mh][r] = 0.f;

    auto issue_chunk = [&](int c, int buf) {
        uint32_t asB = sb + buf * TILE_A;
        uint32_t wsB = sb + SM_W0 + buf * TILE_W;
        const char* wsrc = wimg + c * TILE_W;
#pragma unroll 1
        for (int u = tid; u < 512 + W_SEGS; u += 256) {
            if (u < 512) {
                int s = u >> 3, ko = u & 7;
                cp16(asB + s * 144 + ko * 16,
                     Hr + (size_t)(slot0 + s) * 512 + c * 128 + ko * 16);
            } else {
                int r = u - 512;
                cp16(wsB + r * 16, wsrc + r * 16);
            }
        }
    };

    issue_chunk(0, 0); cp_commit();
    issue_chunk(1, 1); cp_commit();

#pragma unroll 1
    for (int c = 0; c < 4; c++) {
        if (c < 3) cp_wait<1>(); else cp_wait<0>();
        __syncthreads();
        const int buf = c & 1;
        const uint32_t aB = sb + buf * TILE_A + arow_off;
        const uint32_t wB = sb + SM_W0 + buf * TILE_W;
#pragma unroll
        for (int kk4 = 0; kk4 < 4; kk4++) {
            uint32_t a0[4], a1[4];
            ldsm4(a0, aB + kk4 * 32);
            ldsm4(a1, aB + 2304 + kk4 * 32);      // mh=1: +16 rows * 144 B
            const int qb = kk4 * 4 + t4;
#pragma unroll
            for (int g = 0; g < 4; g++) {
                int row = g * 32 + wj * 8 + g4;
                uint32_t b0, b1;
                lds64(b0, b1, wB + (uint32_t)(row * 20 + qb) * 8);
                mma_f16(acc[g][0], a0, b0, b1);
                mma_f16(acc[g][1], a1, b0, b1);
            }
        }
        __syncthreads();
        if (c + 2 < 4) { issue_chunk(c + 2, buf); cp_commit(); }
    }

    // ---- epilogue: LSTM cell, all 4 gates thread-local (8 cells/thread) ----
    __half* HW = d_Hh + (size_t)(wb * 2 + dir) * NW * HID;
    const int jp = j0 + wj * 8 + 2 * t4;
#pragma unroll
    for (int mh = 0; mh < 2; mh++) {
#pragma unroll
        for (int rh = 0; rh < 2; rh++) {
            int s = slot0 + ws * 32 + mh * 16 + rh * 8 + g4;
            if (s >= nact) continue;
            int v = d_chars[dir][t][s];
            const float* Pv = &d_P[((dir << 7) + v) << 10];
            bool last = (t == (int)d_slot_len[s] - 1);
            float* crow = &d_C[((size_t)dir * NW + s) * HID];
            float* frow = &d_Hfin[((size_t)dir * NW + s) * HID];
            __half* hrow = &HW[(size_t)s * HID];
            float hv[2];
#pragma unroll
            for (int cp = 0; cp < 2; cp++) {
                int j = jp + cp;
                float ai = acc[0][mh][rh * 2 + cp] + Pv[j];
                float af = acc[1][mh][rh * 2 + cp] + Pv[256 + j];
                float ag = acc[2][mh][rh * 2 + cp] + Pv[512 + j];
                float ao = acc[3][mh][rh * 2 + cp] + Pv[768 + j];
                float c2 = sigm(af) * crow[j] + sigm(ai) * ftanh(ag);
                float h2 = sigm(ao) * ftanh(c2);
                crow[j] = c2;
                if (last) frow[j] = h2;
                hv[cp] = h2;
            }
            __half2 h2v;
            h2v.x = __float2half_rn(hv[0]);
            h2v.y = __float2half_rn(hv[1]);
            *reinterpret_cast<__half2*>(&hrow[jp]) = h2v;
        }
    }
}

// ---------------- gather output ----------------
__global__ void k_out(float* __restrict__ out) {
    int s = blockIdx.x;
    int tid = threadIdx.x;
    int w = d_word_of_slot[s];
    int dir = tid >> 8, j = tid & 255;
    out[(size_t)w * 512 + tid] = d_Hfin[((size_t)dir * NW + s) * HID + j];
}

// ---------------- launch ----------------
extern "C" void kernel_launch(void* const* d_in, const int* in_sizes, int n_in,
                              void* d_out, int out_size) {
    const int*   char_ids = (const int*)d_in[0];
    const int*   lengths  = (const int*)d_in[1];
    const float* emb      = (const float*)d_in[2];
    const float* WihF = (const float*)d_in[3];
    const float* WhhF = (const float*)d_in[4];
    const float* bihF = (const float*)d_in[5];
    const float* bhhF = (const float*)d_in[6];
    const float* WihB = (const float*)d_in[7];
    const float* WhhB = (const float*)d_in[8];
    const float* bihB = (const float*)d_in[9];
    const float* bhhB = (const float*)d_in[10];
    float* out = (float*)d_out;

    static bool s_init = false;
    if (!s_init) {
        cudaFuncSetAttribute(k_step, cudaFuncAttributeMaxDynamicSharedMemorySize, SM_TOT);
        s_init = true;
    }

    k_setup<<<1, 1024>>>(lengths);
    k_prep<<<2048 + 256, 256>>>(emb, WihF, bihF, bhhF, WihB, bihB, bhhB, WhhF, WhhB);
    k_scatter0<<<NW / 64, 512>>>(lengths, char_ids);
    for (int t = 1; t < MAXLEN; t++)
        k_step<<<dim3(NW / 64, 8, 2), 256, SM_TOT>>>(t);
    k_out<<<NW, 512>>>(out);
}

// round 13
// speedup vs baseline: 3.1498x; 2.0201x over previous
#include <cuda_runtime.h>
#include <cuda_fp16.h>
#include <cstdint>

#define NW     16384
#define MAXLEN 16
#define VOCAB  128
#define EMB    64
#define HID    256
#define G4     1024

// ---------------- static device state (no allocation) ----------------
// P table fp16, gate-interleaved: [dir][v][j 0..255][gate i,f,g,o]
__device__ __align__(16) __half d_P4[(size_t)2 * VOCAB * HID * 4];
__device__ float d_C[(size_t)2 * NW * HID];           // c: [dir][slot][j]
__device__ float d_Hfin[(size_t)2 * NW * HID];        // final h: [dir][slot][j]
// H fp16: [buf][dir][slot][k]
__device__ __align__(16) __half d_Hh[(size_t)2 * 2 * NW * HID];
// W u64-interleaved, chunked: [dir][jb][chunk(4)][128 rows][pitch 20 u64 = 80 halves]
__device__ __align__(16) __half d_Wimg[(size_t)2 * 8 * 4 * 128 * 80];
__device__ int   d_cursor[MAXLEN + 2];
__device__ int   d_offset[MAXLEN + 2];
__device__ int   d_nactive[MAXLEN];
__device__ int   d_word_of_slot[NW];
__device__ unsigned char d_slot_len[NW];
__device__ unsigned char d_chars[2][MAXLEN][NW];

// ---------------- helpers ----------------
__device__ __forceinline__ float sigm(float x) {
    return __fdividef(1.f, 1.f + __expf(-x));
}
__device__ __forceinline__ float ftanh(float x) {
    float e = __expf(-2.f * x);
    return __fdividef(1.f - e, 1.f + e);
}
__device__ __forceinline__ void mma_f16(float c[4], const uint32_t a[4],
                                        uint32_t b0, uint32_t b1) {
    asm volatile(
        "mma.sync.aligned.m16n8k16.row.col.f32.f16.f16.f32 "
        "{%0,%1,%2,%3}, {%4,%5,%6,%7}, {%8,%9}, {%0,%1,%2,%3};"
        : "+f"(c[0]), "+f"(c[1]), "+f"(c[2]), "+f"(c[3])
        : "r"(a[0]), "r"(a[1]), "r"(a[2]), "r"(a[3]), "r"(b0), "r"(b1));
}
__device__ __forceinline__ void ldsm4(uint32_t r[4], uint32_t addr) {
    asm volatile("ldmatrix.sync.aligned.m8n8.x4.shared.b16 {%0,%1,%2,%3}, [%4];"
        : "=r"(r[0]), "=r"(r[1]), "=r"(r[2]), "=r"(r[3]) : "r"(addr));
}
__device__ __forceinline__ void lds64(uint32_t& b0, uint32_t& b1, uint32_t addr) {
    asm volatile("ld.shared.v2.b32 {%0,%1}, [%2];" : "=r"(b0), "=r"(b1) : "r"(addr));
}
__device__ __forceinline__ uint32_t smem_u32(const void* p) {
    uint32_t a;
    asm("{ .reg .u64 t; cvta.to.shared.u64 t, %1; cvt.u32.u64 %0, t; }" : "=r"(a) : "l"(p));
    return a;
}
__device__ __forceinline__ void cp16(uint32_t dst, const void* src) {
    asm volatile("cp.async.cg.shared.global [%0], [%1], 16;" :: "r"(dst), "l"(src) : "memory");
}
__device__ __forceinline__ void cp_commit() {
    asm volatile("cp.async.commit_group;" ::: "memory");
}
template <int N>
__device__ __forceinline__ void cp_wait() {
    asm volatile("cp.async.wait_group %0;" :: "n"(N) : "memory");
}

// ---------------- setup: hist + scan + cursor (one block) ----------------
__global__ void k_setup(const int* __restrict__ lengths) {
    __shared__ int sh[MAXLEN + 2];
    int tid = threadIdx.x;                      // 1024
    if (tid <= MAXLEN + 1) sh[tid] = 0;
    __syncthreads();
    for (int w = tid; w < NW; w += 1024) atomicAdd(&sh[lengths[w]], 1);
    __syncthreads();
    if (tid == 0) {
        int off = 0;
        for (int L = MAXLEN; L >= 1; L--) { d_offset[L] = off; off += sh[L]; }
        for (int t = 0; t < MAXLEN; t++) {
            int n = 0;
            for (int L = t + 1; L <= MAXLEN; L++) n += sh[L];
            d_nactive[t] = n;
        }
    }
    if (tid <= MAXLEN + 1) d_cursor[tid] = 0;
}

// ---------------- prep: W u64-interleaved chunked image + P4 table ----------------
__global__ void k_prep(const float* __restrict__ emb,
                       const float* __restrict__ WihF, const float* __restrict__ bihF,
                       const float* __restrict__ bhhF,
                       const float* __restrict__ WihB, const float* __restrict__ bihB,
                       const float* __restrict__ bhhB,
                       const float* __restrict__ WhhF, const float* __restrict__ WhhB) {
    if (blockIdx.x < 2048) {
        int i = blockIdx.x * 256 + threadIdx.x;    // 2*1024*256
        int dir = i >> 18;
        int e = i & 0x3FFFF;
        int row = e >> 8, k = e & 255;
        int g = row >> 8, j = row & 255;
        int jb = j >> 5, jl = j & 31;
        int r128 = g * 32 + jl;
        int ch = k >> 6, kl = k & 63;
        int q = (kl >> 4) * 4 + ((kl & 7) >> 1);
        int pos = (kl & 1) + (((kl & 15) >= 8) ? 2 : 0);
        float x = (dir ? WhhB : WhhF)[(size_t)row * 256 + k];
        d_Wimg[(((size_t)((dir * 8 + jb) * 4 + ch) * 128 + r128) * 20 + q) * 4 + pos]
            = __float2half_rn(x);
    } else {
        int bid = blockIdx.x - 2048;
        int v = bid & 127, d = bid >> 7;
        const float* Wih = d ? WihB : WihF;
        const float* bih = d ? bihB : bihF;
        const float* bhh = d ? bhhB : bhhF;
        __shared__ float esm[EMB];
        if (threadIdx.x < EMB) esm[threadIdx.x] = emb[v * EMB + threadIdx.x];
        __syncthreads();
#pragma unroll
        for (int q = 0; q < 4; q++) {
            int j = threadIdx.x + q * 256;         // 0..1023 gate-major row
            const float* wr = &Wih[j * EMB];
            float s = 0.f;
#pragma unroll
            for (int k = 0; k < EMB; k += 4) {
                float4 wv = *reinterpret_cast<const float4*>(&wr[k]);
                s += esm[k] * wv.x + esm[k + 1] * wv.y + esm[k + 2] * wv.z + esm[k + 3] * wv.w;
            }
            int g = j >> 8, jc = j & 255;
            d_P4[(((size_t)(d * VOCAB + v) * HID + jc) << 2) + g]
                = __float2half_rn(s + bih[j] + bhh[j]);
        }
    }
}

// ---------------- scatter + step 0 (h0 = 0 -> gates = P[char]) ----------------
__global__ void __launch_bounds__(512)
k_scatter0(const int* __restrict__ lengths, const int* __restrict__ char_ids) {
    int tid = threadIdx.x;
    int wloc = tid >> 3, sub = tid & 7;
    int w = blockIdx.x * 64 + wloc;
    __shared__ int spos[64];
    int len = lengths[w];
    if (sub == 0) {
        int pos = d_offset[len] + atomicAdd(&d_cursor[len], 1);
        spos[wloc] = pos;
        d_word_of_slot[pos] = w;
        d_slot_len[pos] = (unsigned char)len;
#pragma unroll
        for (int t = 0; t < MAXLEN; t++) {
            d_chars[0][t][pos] = (unsigned char)char_ids[w * MAXLEN + t];
            int r = len - 1 - t; if (r < 0) r = 0;
            d_chars[1][t][pos] = (unsigned char)char_ids[w * MAXLEN + r];
        }
    }
    __syncthreads();
    int pos = spos[wloc];
    int dir = sub >> 2;
    int j0 = (sub & 3) * 64;
    int v = char_ids[w * MAXLEN + (dir ? (len - 1) : 0)];
    const __half* Pv = d_P4 + (((size_t)(dir * VOCAB + v) * HID) << 2);
    bool last = (len == 1);
    float* crow = &d_C[((size_t)dir * NW + pos) * HID];
    float* frow = &d_Hfin[((size_t)dir * NW + pos) * HID];
    __half* hrow = d_Hh + ((size_t)(2 + dir) * NW + pos) * HID;   // buf 1
#pragma unroll 2
    for (int q = 0; q < 64; q += 2) {
        float hv[2];
        uint4 pk = *reinterpret_cast<const uint4*>(&Pv[(j0 + q) << 2]);
        const __half2* ph = reinterpret_cast<const __half2*>(&pk);
#pragma unroll
        for (int u = 0; u < 2; u++) {
            int j = j0 + q + u;
            float pi = __half2float(ph[2 * u].x);
            float pg = __half2float(ph[2 * u + 1].x);
            float po = __half2float(ph[2 * u + 1].y);
            float c1 = sigm(pi) * ftanh(pg);
            float h1 = sigm(po) * ftanh(c1);
            crow[j] = c1;
            if (last) frow[j] = h1;
            hv[u] = h1;
        }
        __half2 h2v; h2v.x = __float2half_rn(hv[0]); h2v.y = __float2half_rn(hv[1]);
        *reinterpret_cast<__half2*>(&hrow[j0 + q]) = h2v;
    }
}

// ---------------- fused recurrent step (t >= 1) ----------------
// Block: 64 slots x 32 j x 4 gates, 8 warps. Warp tile 32 slots x 32 n (square).
#define TILE_A  9216                           // 64 * 144
#define TILE_W  20480                          // 128 * 160
#define SM_W0   (2 * TILE_A)                   // 18432
#define SM_TOT  (SM_W0 + 2 * TILE_W)           // 59392
#define W_SEGS  (TILE_W / 16)                  // 1280

__global__ void __launch_bounds__(256, 3) k_step(int t) {
    const int nact = d_nactive[t];
    const int slot0 = blockIdx.x * 64;
    if (slot0 >= nact) return;
    const int jb = blockIdx.y, j0 = jb * 32;
    const int dir = blockIdx.z;
    const int rb = t & 1, wb = rb ^ 1;

    extern __shared__ __align__(16) char smem[];
    const uint32_t sb = smem_u32(smem);
    const char* __restrict__ Hr = (const char*)(d_Hh + (size_t)(rb * 2 + dir) * NW * HID);
    const char* wimg = (const char*)d_Wimg + (size_t)(dir * 8 + jb) * 4 * TILE_W;

    const int tid = threadIdx.x;
    const int warp = tid >> 5, lane = tid & 31;
    const int ws = warp & 1, wj = warp >> 1;
    const int g4 = lane >> 2, t4 = lane & 3;

    const uint32_t arow_off = (uint32_t)(ws * 32 + (lane & 15)) * 144 + ((lane & 16) ? 16 : 0);

    float acc[4][2][4];                        // [gate][mh][frag]
#pragma unroll
    for (int g = 0; g < 4; g++)
#pragma unroll
        for (int mh = 0; mh < 2; mh++)
#pragma unroll
            for (int r = 0; r < 4; r++) acc[g][mh][r] = 0.f;

    auto issue_chunk = [&](int c, int buf) {
        uint32_t asB = sb + buf * TILE_A;
        uint32_t wsB = sb + SM_W0 + buf * TILE_W;
        const char* wsrc = wimg + c * TILE_W;
#pragma unroll 1
        for (int u = tid; u < 512 + W_SEGS; u += 256) {
            if (u < 512) {
                int s = u >> 3, ko = u & 7;
                cp16(asB + s * 144 + ko * 16,
                     Hr + (size_t)(slot0 + s) * 512 + c * 128 + ko * 16);
            } else {
                int r = u - 512;
                cp16(wsB + r * 16, wsrc + r * 16);
            }
        }
    };

    issue_chunk(0, 0); cp_commit();
    issue_chunk(1, 1); cp_commit();

#pragma unroll 1
    for (int c = 0; c < 4; c++) {
        if (c < 3) cp_wait<1>(); else cp_wait<0>();
        __syncthreads();
        const int buf = c & 1;
        const uint32_t aB = sb + buf * TILE_A + arow_off;
        const uint32_t wB = sb + SM_W0 + buf * TILE_W;
#pragma unroll
        for (int kk4 = 0; kk4 < 4; kk4++) {
            uint32_t a0[4], a1[4];
            ldsm4(a0, aB + kk4 * 32);
            ldsm4(a1, aB + 2304 + kk4 * 32);      // mh=1: +16 rows * 144 B
            const int qb = kk4 * 4 + t4;
#pragma unroll
            for (int g = 0; g < 4; g++) {
                int row = g * 32 + wj * 8 + g4;
                uint32_t b0, b1;
                lds64(b0, b1, wB + (uint32_t)(row * 20 + qb) * 8);
                mma_f16(acc[g][0], a0, b0, b1);
                mma_f16(acc[g][1], a1, b0, b1);
            }
        }
        __syncthreads();
        if (c + 2 < 4) { issue_chunk(c + 2, buf); cp_commit(); }
    }

    // ---- epilogue: LSTM cell, all 4 gates thread-local (8 cells/thread) ----
    __half* HW = d_Hh + (size_t)(wb * 2 + dir) * NW * HID;
    const int jp = j0 + wj * 8 + 2 * t4;
#pragma unroll
    for (int mh = 0; mh < 2; mh++) {
#pragma unroll
        for (int rh = 0; rh < 2; rh++) {
            int s = slot0 + ws * 32 + mh * 16 + rh * 8 + g4;
            if (s >= nact) continue;
            int v = d_chars[dir][t][s];
            bool last = (t == (int)d_slot_len[s] - 1);
            float* crow = &d_C[((size_t)dir * NW + s) * HID];
            float* frow = &d_Hfin[((size_t)dir * NW + s) * HID];
            __half* hrow = &HW[(size_t)s * HID];
            // one 16B gather: 4 gates x 2 cells, fp16
            uint4 pk = *reinterpret_cast<const uint4*>(
                &d_P4[((((size_t)(dir * VOCAB + v) * HID) + jp) << 2)]);
            const __half2* ph = reinterpret_cast<const __half2*>(&pk);
            float2 cc = *reinterpret_cast<const float2*>(&crow[jp]);
            float cin[2] = {cc.x, cc.y};
            float hv[2], cv[2];
#pragma unroll
            for (int cp = 0; cp < 2; cp++) {
                float ai = acc[0][mh][rh * 2 + cp] + __half2float(ph[2 * cp].x);
                float af = acc[1][mh][rh * 2 + cp] + __half2float(ph[2 * cp].y);
                float ag = acc[2][mh][rh * 2 + cp] + __half2float(ph[2 * cp + 1].x);
                float ao = acc[3][mh][rh * 2 + cp] + __half2float(ph[2 * cp + 1].y);
                float c2 = sigm(af) * cin[cp] + sigm(ai) * ftanh(ag);
                float h2 = sigm(ao) * ftanh(c2);
                cv[cp] = c2;
                hv[cp] = h2;
            }
            *reinterpret_cast<float2*>(&crow[jp]) = make_float2(cv[0], cv[1]);
            if (last)
                *reinterpret_cast<float2*>(&frow[jp]) = make_float2(hv[0], hv[1]);
            __half2 h2v;
            h2v.x = __float2half_rn(hv[0]);
            h2v.y = __float2half_rn(hv[1]);
            *reinterpret_cast<__half2*>(&hrow[jp]) = h2v;
        }
    }
}

// ---------------- gather output ----------------
__global__ void k_out(float* __restrict__ out) {
    int s = blockIdx.x;
    int tid = threadIdx.x;
    int w = d_word_of_slot[s];
    int dir = tid >> 8, j = tid & 255;
    out[(size_t)w * 512 + tid] = d_Hfin[((size_t)dir * NW + s) * HID + j];
}

// ---------------- launch ----------------
extern "C" void kernel_launch(void* const* d_in, const int* in_sizes, int n_in,
                              void* d_out, int out_size) {
    const int*   char_ids = (const int*)d_in[0];
    const int*   lengths  = (const int*)d_in[1];
    const float* emb      = (const float*)d_in[2];
    const float* WihF = (const float*)d_in[3];
    const float* WhhF = (const float*)d_in[4];
    const float* bihF = (const float*)d_in[5];
    const float* bhhF = (const float*)d_in[6];
    const float* WihB = (const float*)d_in[7];
    const float* WhhB = (const float*)d_in[8];
    const float* bihB = (const float*)d_in[9];
    const float* bhhB = (const float*)d_in[10];
    float* out = (float*)d_out;

    static bool s_init = false;
    if (!s_init) {
        cudaFuncSetAttribute(k_step, cudaFuncAttributeMaxDynamicSharedMemorySize, SM_TOT);
        s_init = true;
    }

    k_setup<<<1, 1024>>>(lengths);
    k_prep<<<2048 + 256, 256>>>(emb, WihF, bihF, bhhF, WihB, bihB, bhhB, WhhF, WhhB);
    k_scatter0<<<NW / 64, 512>>>(lengths, char_ids);
    for (int t = 1; t < MAXLEN; t++)
        k_step<<<dim3(NW / 64, 8, 2), 256, SM_TOT>>>(t);
    k_out<<<NW, 512>>>(out);
}

// round 14
// speedup vs baseline: 3.4364x; 1.0910x over previous
#include <cuda_runtime.h>
#include <cuda_fp16.h>
#include <cstdint>

#define NW     16384
#define MAXLEN 16
#define VOCAB  128
#define EMB    64
#define HID    256
#define G4     1024

// ---------------- static device state (no allocation) ----------------
// P table fp16, gate-interleaved: [dir][v][j 0..255][gate i,f,g,o]
__device__ __align__(16) __half d_P4[(size_t)2 * VOCAB * HID * 4];
__device__ float d_C[(size_t)2 * NW * HID];           // c: [dir][slot][j]
__device__ float d_Hfin[(size_t)2 * NW * HID];        // final h: [dir][slot][j]
// H fp16: [buf][dir][slot][k]
__device__ __align__(16) __half d_Hh[(size_t)2 * 2 * NW * HID];
// W u64-interleaved, chunked: [dir][jb][chunk(4)][128 rows][pitch 20 u64 = 80 halves]
__device__ __align__(16) __half d_Wimg[(size_t)2 * 8 * 4 * 128 * 80];
__device__ int   d_cursor[MAXLEN + 2];
__device__ int   d_offset[MAXLEN + 2];
__device__ int   d_nactive[MAXLEN];
__device__ int   d_word_of_slot[NW];
__device__ unsigned char d_slot_len[NW];
__device__ unsigned char d_chars[2][MAXLEN][NW];

// ---------------- helpers ----------------
__device__ __forceinline__ float sigm(float x) {
    return __fdividef(1.f, 1.f + __expf(-x));
}
__device__ __forceinline__ float ftanh(float x) {
    float e = __expf(-2.f * x);
    return __fdividef(1.f - e, 1.f + e);
}
__device__ __forceinline__ void mma_f16(float c[4], const uint32_t a[4],
                                        uint32_t b0, uint32_t b1) {
    asm volatile(
        "mma.sync.aligned.m16n8k16.row.col.f32.f16.f16.f32 "
        "{%0,%1,%2,%3}, {%4,%5,%6,%7}, {%8,%9}, {%0,%1,%2,%3};"
        : "+f"(c[0]), "+f"(c[1]), "+f"(c[2]), "+f"(c[3])
        : "r"(a[0]), "r"(a[1]), "r"(a[2]), "r"(a[3]), "r"(b0), "r"(b1));
}
__device__ __forceinline__ void ldsm4(uint32_t r[4], uint32_t addr) {
    asm volatile("ldmatrix.sync.aligned.m8n8.x4.shared.b16 {%0,%1,%2,%3}, [%4];"
        : "=r"(r[0]), "=r"(r[1]), "=r"(r[2]), "=r"(r[3]) : "r"(addr));
}
__device__ __forceinline__ void lds64(uint32_t& b0, uint32_t& b1, uint32_t addr) {
    asm volatile("ld.shared.v2.b32 {%0,%1}, [%2];" : "=r"(b0), "=r"(b1) : "r"(addr));
}
__device__ __forceinline__ uint32_t smem_u32(const void* p) {
    uint32_t a;
    asm("{ .reg .u64 t; cvta.to.shared.u64 t, %1; cvt.u32.u64 %0, t; }" : "=r"(a) : "l"(p));
    return a;
}
__device__ __forceinline__ void cp16(uint32_t dst, const void* src) {
    asm volatile("cp.async.cg.shared.global [%0], [%1], 16;" :: "r"(dst), "l"(src) : "memory");
}
__device__ __forceinline__ void cp_commit() {
    asm volatile("cp.async.commit_group;" ::: "memory");
}
template <int N>
__device__ __forceinline__ void cp_wait() {
    asm volatile("cp.async.wait_group %0;" :: "n"(N) : "memory");
}
__device__ __forceinline__ void gdc_wait() {
    asm volatile("griddepcontrol.wait;" ::: "memory");
}
__device__ __forceinline__ void gdc_launch() {
    asm volatile("griddepcontrol.launch_dependents;" ::: "memory");
}

// ---------------- setup: hist + scan + cursor (one block) ----------------
__global__ void k_setup(const int* __restrict__ lengths) {
    __shared__ int sh[MAXLEN + 2];
    int tid = threadIdx.x;                      // 1024
    if (tid <= MAXLEN + 1) sh[tid] = 0;
    __syncthreads();
    for (int w = tid; w < NW; w += 1024) atomicAdd(&sh[lengths[w]], 1);
    __syncthreads();
    if (tid == 0) {
        int off = 0;
        for (int L = MAXLEN; L >= 1; L--) { d_offset[L] = off; off += sh[L]; }
        for (int t = 0; t < MAXLEN; t++) {
            int n = 0;
            for (int L = t + 1; L <= MAXLEN; L++) n += sh[L];
            d_nactive[t] = n;
        }
    }
    if (tid <= MAXLEN + 1) d_cursor[tid] = 0;
}

// ---------------- prep: W u64-interleaved chunked image + P4 table ----------------
__global__ void k_prep(const float* __restrict__ emb,
                       const float* __restrict__ WihF, const float* __restrict__ bihF,
                       const float* __restrict__ bhhF,
                       const float* __restrict__ WihB, const float* __restrict__ bihB,
                       const float* __restrict__ bhhB,
                       const float* __restrict__ WhhF, const float* __restrict__ WhhB) {
    if (blockIdx.x < 2048) {
        int i = blockIdx.x * 256 + threadIdx.x;    // 2*1024*256
        int dir = i >> 18;
        int e = i & 0x3FFFF;
        int row = e >> 8, k = e & 255;
        int g = row >> 8, j = row & 255;
        int jb = j >> 5, jl = j & 31;
        int r128 = g * 32 + jl;
        int ch = k >> 6, kl = k & 63;
        int q = (kl >> 4) * 4 + ((kl & 7) >> 1);
        int pos = (kl & 1) + (((kl & 15) >= 8) ? 2 : 0);
        float x = (dir ? WhhB : WhhF)[(size_t)row * 256 + k];
        d_Wimg[(((size_t)((dir * 8 + jb) * 4 + ch) * 128 + r128) * 20 + q) * 4 + pos]
            = __float2half_rn(x);
    } else {
        int bid = blockIdx.x - 2048;
        int v = bid & 127, d = bid >> 7;
        const float* Wih = d ? WihB : WihF;
        const float* bih = d ? bihB : bihF;
        const float* bhh = d ? bhhB : bhhF;
        __shared__ float esm[EMB];
        if (threadIdx.x < EMB) esm[threadIdx.x] = emb[v * EMB + threadIdx.x];
        __syncthreads();
#pragma unroll
        for (int q = 0; q < 4; q++) {
            int j = threadIdx.x + q * 256;         // 0..1023 gate-major row
            const float* wr = &Wih[j * EMB];
            float s = 0.f;
#pragma unroll
            for (int k = 0; k < EMB; k += 4) {
                float4 wv = *reinterpret_cast<const float4*>(&wr[k]);
                s += esm[k] * wv.x + esm[k + 1] * wv.y + esm[k + 2] * wv.z + esm[k + 3] * wv.w;
            }
            int g = j >> 8, jc = j & 255;
            d_P4[(((size_t)(d * VOCAB + v) * HID + jc) << 2) + g]
                = __float2half_rn(s + bih[j] + bhh[j]);
        }
    }
}

// ---------------- scatter + step 0 (h0 = 0 -> gates = P[char]) ----------------
__global__ void __launch_bounds__(512)
k_scatter0(const int* __restrict__ lengths, const int* __restrict__ char_ids) {
    int tid = threadIdx.x;
    int wloc = tid >> 3, sub = tid & 7;
    int w = blockIdx.x * 64 + wloc;
    __shared__ int spos[64];
    int len = lengths[w];
    if (sub == 0) {
        int pos = d_offset[len] + atomicAdd(&d_cursor[len], 1);
        spos[wloc] = pos;
        d_word_of_slot[pos] = w;
        d_slot_len[pos] = (unsigned char)len;
    }
    __syncthreads();
    int pos = spos[wloc];
    // chars transpose parallel across subs: each sub handles 2 t values
#pragma unroll
    for (int tt = sub * 2; tt < sub * 2 + 2; tt++) {
        d_chars[0][tt][pos] = (unsigned char)char_ids[w * MAXLEN + tt];
        int r = len - 1 - tt; if (r < 0) r = 0;
        d_chars[1][tt][pos] = (unsigned char)char_ids[w * MAXLEN + r];
    }
    int dir = sub >> 2;
    int j0 = (sub & 3) * 64;
    int v = char_ids[w * MAXLEN + (dir ? (len - 1) : 0)];
    const __half* Pv = d_P4 + (((size_t)(dir * VOCAB + v) * HID) << 2);
    bool last = (len == 1);
    float* crow = &d_C[((size_t)dir * NW + pos) * HID];
    float* frow = &d_Hfin[((size_t)dir * NW + pos) * HID];
    __half* hrow = d_Hh + ((size_t)(2 + dir) * NW + pos) * HID;   // buf 1
#pragma unroll 2
    for (int q = 0; q < 64; q += 2) {
        float hv[2];
        uint4 pk = *reinterpret_cast<const uint4*>(&Pv[(j0 + q) << 2]);
        const __half2* ph = reinterpret_cast<const __half2*>(&pk);
#pragma unroll
        for (int u = 0; u < 2; u++) {
            int j = j0 + q + u;
            float pi = __half2float(ph[2 * u].x);
            float pg = __half2float(ph[2 * u + 1].x);
            float po = __half2float(ph[2 * u + 1].y);
            float c1 = sigm(pi) * ftanh(pg);
            float h1 = sigm(po) * ftanh(c1);
            crow[j] = c1;
            if (last) frow[j] = h1;
            hv[u] = h1;
        }
        __half2 h2v; h2v.x = __float2half_rn(hv[0]); h2v.y = __float2half_rn(hv[1]);
        *reinterpret_cast<__half2*>(&hrow[j0 + q]) = h2v;
    }
}

// ---------------- fused recurrent step (t >= 1) ----------------
// Block: 64 slots x 32 j x 4 gates, 8 warps. Warp tile 32 slots x 32 n (square).
#define TILE_A  9216                           // 64 * 144
#define TILE_W  20480                          // 128 * 160
#define SM_W0   (2 * TILE_A)                   // 18432
#define SM_TOT  (SM_W0 + 2 * TILE_W)           // 59392

__global__ void __launch_bounds__(256, 3) k_step(int t) {
    gdc_wait();                                // PDL: prior step's H fully visible
    const int nact = d_nactive[t];
    const int slot0 = blockIdx.x * 64;
    if (slot0 >= nact) { gdc_launch(); return; }
    const int jb = blockIdx.y, j0 = jb * 32;
    const int dir = blockIdx.z;
    const int rb = t & 1, wb = rb ^ 1;

    extern __shared__ __align__(16) char smem[];
    const uint32_t sb = smem_u32(smem);
    const char* __restrict__ Hr = (const char*)(d_Hh + (size_t)(rb * 2 + dir) * NW * HID);
    const char* wimg = (const char*)d_Wimg + (size_t)(dir * 8 + jb) * 4 * TILE_W;

    const int tid = threadIdx.x;
    const int warp = tid >> 5, lane = tid & 31;
    const int ws = warp & 1, wj = warp >> 1;
    const int g4 = lane >> 2, t4 = lane & 3;

    const uint32_t arow_off = (uint32_t)(ws * 32 + (lane & 15)) * 144 + ((lane & 16) ? 16 : 0);

    float acc[4][2][4];                        // [gate][mh][frag]
#pragma unroll
    for (int g = 0; g < 4; g++)
#pragma unroll
        for (int mh = 0; mh < 2; mh++)
#pragma unroll
            for (int r = 0; r < 4; r++) acc[g][mh][r] = 0.f;

    // branch-free staging: 2 A segs + 5 W segs per thread
    const int sA0 = tid >> 3, koA = (tid & 7) * 16;
    auto issue_chunk = [&](int c, int buf) {
        uint32_t asB = sb + buf * TILE_A;
        uint32_t wsB = sb + SM_W0 + buf * TILE_W;
        const char* wsrc = wimg + c * TILE_W;
        cp16(asB + sA0 * 144 + koA,
             Hr + (size_t)(slot0 + sA0) * 512 + c * 128 + koA);
        cp16(asB + (sA0 + 32) * 144 + koA,
             Hr + (size_t)(slot0 + sA0 + 32) * 512 + c * 128 + koA);
#pragma unroll
        for (int i = 0; i < 5; i++) {
            int r = (tid + i * 256) * 16;
            cp16(wsB + r, wsrc + r);
        }
    };

    issue_chunk(0, 0); cp_commit();
    issue_chunk(1, 1); cp_commit();

#pragma unroll 1
    for (int c = 0; c < 4; c++) {
        if (c < 3) cp_wait<1>(); else cp_wait<0>();
        __syncthreads();
        const int buf = c & 1;
        const uint32_t aB = sb + buf * TILE_A + arow_off;
        const uint32_t wB = sb + SM_W0 + buf * TILE_W;
#pragma unroll
        for (int kk4 = 0; kk4 < 4; kk4++) {
            uint32_t a0[4], a1[4];
            ldsm4(a0, aB + kk4 * 32);
            ldsm4(a1, aB + 2304 + kk4 * 32);      // mh=1: +16 rows * 144 B
            const int qb = kk4 * 4 + t4;
#pragma unroll
            for (int g = 0; g < 4; g++) {
                int row = g * 32 + wj * 8 + g4;
                uint32_t b0, b1;
                lds64(b0, b1, wB + (uint32_t)(row * 20 + qb) * 8);
                mma_f16(acc[g][0], a0, b0, b1);
                mma_f16(acc[g][1], a1, b0, b1);
            }
        }
        __syncthreads();
        if (c + 2 < 4) { issue_chunk(c + 2, buf); cp_commit(); }
    }

    // ---- epilogue: LSTM cell, all 4 gates thread-local (8 cells/thread) ----
    __half* HW = d_Hh + (size_t)(wb * 2 + dir) * NW * HID;
    const int jp = j0 + wj * 8 + 2 * t4;
#pragma unroll
    for (int mh = 0; mh < 2; mh++) {
#pragma unroll
        for (int rh = 0; rh < 2; rh++) {
            int s = slot0 + ws * 32 + mh * 16 + rh * 8 + g4;
            if (s >= nact) continue;
            int v = d_chars[dir][t][s];
            bool last = (t == (int)d_slot_len[s] - 1);
            float* crow = &d_C[((size_t)dir * NW + s) * HID];
            float* frow = &d_Hfin[((size_t)dir * NW + s) * HID];
            __half* hrow = &HW[(size_t)s * HID];
            uint4 pk = *reinterpret_cast<const uint4*>(
                &d_P4[((((size_t)(dir * VOCAB + v) * HID) + jp) << 2)]);
            const __half2* ph = reinterpret_cast<const __half2*>(&pk);
            float2 cc = *reinterpret_cast<const float2*>(&crow[jp]);
            float cin[2] = {cc.x, cc.y};
            float hv[2], cv[2];
#pragma unroll
            for (int cp = 0; cp < 2; cp++) {
                float ai = acc[0][mh][rh * 2 + cp] + __half2float(ph[2 * cp].x);
                float af = acc[1][mh][rh * 2 + cp] + __half2float(ph[2 * cp].y);
                float ag = acc[2][mh][rh * 2 + cp] + __half2float(ph[2 * cp + 1].x);
                float ao = acc[3][mh][rh * 2 + cp] + __half2float(ph[2 * cp + 1].y);
                float c2 = sigm(af) * cin[cp] + sigm(ai) * ftanh(ag);
                float h2 = sigm(ao) * ftanh(c2);
                cv[cp] = c2;
                hv[cp] = h2;
            }
            *reinterpret_cast<float2*>(&crow[jp]) = make_float2(cv[0], cv[1]);
            if (last)
                *reinterpret_cast<float2*>(&frow[jp]) = make_float2(hv[0], hv[1]);
            __half2 h2v;
            h2v.x = __float2half_rn(hv[0]);
            h2v.y = __float2half_rn(hv[1]);
            *reinterpret_cast<__half2*>(&hrow[jp]) = h2v;
        }
    }
    gdc_launch();
}

// ---------------- gather output ----------------
__global__ void k_out(float* __restrict__ out) {
    gdc_wait();
    int s = blockIdx.x;
    int tid = threadIdx.x;
    int w = d_word_of_slot[s];
    int dir = tid >> 8, j = tid & 255;
    out[(size_t)w * 512 + tid] = d_Hfin[((size_t)dir * NW + s) * HID + j];
}

// ---------------- launch ----------------
extern "C" void kernel_launch(void* const* d_in, const int* in_sizes, int n_in,
                              void* d_out, int out_size) {
    const int*   char_ids = (const int*)d_in[0];
    const int*   lengths  = (const int*)d_in[1];
    const float* emb      = (const float*)d_in[2];
    const float* WihF = (const float*)d_in[3];
    const float* WhhF = (const float*)d_in[4];
    const float* bihF = (const float*)d_in[5];
    const float* bhhF = (const float*)d_in[6];
    const float* WihB = (const float*)d_in[7];
    const float* WhhB = (const float*)d_in[8];
    const float* bihB = (const float*)d_in[9];
    const float* bhhB = (const float*)d_in[10];
    float* out = (float*)d_out;

    static bool s_init = false;
    if (!s_init) {
        cudaFuncSetAttribute(k_step, cudaFuncAttributeMaxDynamicSharedMemorySize, SM_TOT);
        s_init = true;
    }

    k_setup<<<1, 1024>>>(lengths);
    k_prep<<<2048 + 256, 256>>>(emb, WihF, bihF, bhhF, WihB, bihB, bhhB, WhhF, WhhB);
    k_scatter0<<<NW / 64, 512>>>(lengths, char_ids);

    // PDL launches for the dependent step chain
    cudaLaunchAttribute pdl[1];
    pdl[0].id = cudaLaunchAttributeProgrammaticStreamSerialization;
    pdl[0].val.programmaticStreamSerializationAllowed = 1;
    for (int t = 1; t < MAXLEN; t++) {
        cudaLaunchConfig_t cfg = {};
        cfg.gridDim = dim3(NW / 64, 8, 2);
        cfg.blockDim = dim3(256, 1, 1);
        cfg.dynamicSmemBytes = SM_TOT;
        cfg.stream = 0;
        cfg.attrs = pdl;
        cfg.numAttrs = 1;
        cudaLaunchKernelEx(&cfg, k_step, t);
    }
    {
        cudaLaunchConfig_t cfg = {};
        cfg.gridDim = dim3(NW, 1, 1);
        cfg.blockDim = dim3(512, 1, 1);
        cfg.dynamicSmemBytes = 0;
        cfg.stream = 0;
        cfg.attrs = pdl;
        cfg.numAttrs = 1;
        cudaLaunchKernelEx(&cfg, k_out, out);
    }
}